// round 3
// baseline (speedup 1.0000x reference)
#include <cuda_runtime.h>
#include <math.h>

#define NE 100000
#define NR 400
#define DI 200
#define DO 400
#define NEDGE 600000
#define HALFE 300000
#define NB 1024
#define NGROUP 800
#define BN_EPS 1e-5f

typedef unsigned long long u64;

// ---------------- device scratch ----------------
__device__ float g_M[(size_t)NGROUP * DI * DO];   // TRANSPOSED: per matrix [o][t], t fast
__device__ float g_Mloop[DO * DI];                // transposed
__device__ float g_x[(size_t)NE * DO];
__device__ float g_stats[2 * DO];
__device__ float g_scale[DO];
__device__ float g_shift[DO];
__device__ float g_r[NR * DO];
__device__ float g_obj[NB * DO];
__device__ int   g_hist[NGROUP];
__device__ int   g_off[NGROUP + 1];
__device__ int   g_pos[NGROUP];
__device__ int   g_eidx[NEDGE];

// ---------------- f32x2 helpers ----------------
__device__ __forceinline__ u64 ffma2(u64 a, u64 b, u64 c) {
    u64 d;
    asm("fma.rn.f32x2 %0, %1, %2, %3;" : "=l"(d) : "l"(a), "l"(b), "l"(c));
    return d;
}
__device__ __forceinline__ u64 pack2(float x) {
    unsigned xi = __float_as_uint(x);
    u64 d;
    asm("mov.b64 %0, {%1, %2};" : "=l"(d) : "r"(xi), "r"(xi));
    return d;
}
__device__ __forceinline__ float2 unpack2(u64 v) {
    unsigned lo, hi;
    asm("mov.b64 {%0, %1}, %2;" : "=r"(lo), "=r"(hi) : "l"(v));
    return make_float2(__uint_as_float(lo), __uint_as_float(hi));
}
__device__ __forceinline__ void red4(float* p, float a, float b, float c, float d) {
    asm volatile("red.global.add.v4.f32 [%0], {%1,%2,%3,%4};"
                 :: "l"(p), "f"(a), "f"(b), "f"(c), "f"(d) : "memory");
}

// ---------------- zero scratch ----------------
__global__ void k_zero() {
    const size_t n4 = (size_t)NE * DO / 4;
    float4* p = reinterpret_cast<float4*>(g_x);
    const float4 z = make_float4(0.f, 0.f, 0.f, 0.f);
    for (size_t i = (size_t)blockIdx.x * blockDim.x + threadIdx.x; i < n4;
         i += (size_t)gridDim.x * blockDim.x)
        p[i] = z;
    int gid = blockIdx.x * blockDim.x + threadIdx.x;
    if (gid < NGROUP) g_hist[gid] = 0;
    if (gid < 2 * DO) g_stats[gid] = 0.f;
}

// ---------------- edge grouping ----------------
__global__ void k_hist(const int* __restrict__ et) {
    int e = blockIdx.x * blockDim.x + threadIdx.x;
    if (e < NEDGE) atomicAdd(&g_hist[et[e] + (e < HALFE ? 0 : 400)], 1);
}

__global__ void k_scan() {
    __shared__ int s[NGROUP];
    int i = threadIdx.x;
    if (i < NGROUP) s[i] = g_hist[i];
    __syncthreads();
    for (int d = 1; d < NGROUP; d <<= 1) {
        int v = 0;
        if (i < NGROUP && i >= d) v = s[i - d];
        __syncthreads();
        if (i < NGROUP && i >= d) s[i] += v;
        __syncthreads();
    }
    if (i < NGROUP) {
        int excl = s[i] - g_hist[i];
        g_off[i] = excl;
        g_pos[i] = excl;
        if (i == NGROUP - 1) g_off[NGROUP] = s[i];
    }
}

__global__ void k_scatter(const int* __restrict__ et) {
    int e = blockIdx.x * blockDim.x + threadIdx.x;
    if (e < NEDGE) {
        int p = atomicAdd(&g_pos[et[e] + (e < HALFE ? 0 : 400)], 1);
        g_eidx[p] = e;
    }
}

// ---------------- M precompute: M'[o,t] = (1/3) sum_j b[(t+j)%200] W[j,o] ----------------
__global__ void __launch_bounds__(256) k_M(
    const float* __restrict__ rel_emb, const float* __restrict__ in_w,
    const float* __restrict__ out_w, const float* __restrict__ loop_w,
    const float* __restrict__ loop_rel) {
    __shared__ float bb[464];
    __shared__ float tr[64][65];
    int m = blockIdx.y;
    const float* bsrc;
    const float* W;
    float* outp;
    if (m < 800) {
        int h = m / 400, r = m - h * 400;
        bsrc = rel_emb + (size_t)r * DI;
        W = h ? out_w : in_w;
        outp = g_M + (size_t)m * (DI * DO);
    } else {
        bsrc = loop_rel;
        W = loop_w;
        outp = g_Mloop;
    }
    int tid = threadIdx.x;
    for (int s = tid; s < 464; s += 256) bb[s] = bsrc[s % DI];
    __syncthreads();

    int te = tid >> 4, to = tid & 15;
    int t0 = blockIdx.x * 64;
    const float S = 1.f / 3.f;

    for (int ot = 0; ot < 7; ++ot) {
        int o0 = ot * 64;
        int n0 = o0 + to * 4;
        if (n0 < DO) {
            u64 acc[4][2] = {};
            for (int j = 0; j < DI; j += 4) {
#pragma unroll
                for (int jj = 0; jj < 4; jj++) {
                    ulonglong2 w2 = *(const ulonglong2*)&W[(size_t)(j + jj) * DO + n0];
#pragma unroll
                    for (int i = 0; i < 4; i++) {
                        u64 a2 = pack2(bb[t0 + te * 4 + i + j + jj]);
                        acc[i][0] = ffma2(a2, w2.x, acc[i][0]);
                        acc[i][1] = ffma2(a2, w2.y, acc[i][1]);
                    }
                }
            }
#pragma unroll
            for (int i = 0; i < 4; i++) {
                float2 u0 = unpack2(acc[i][0]);
                float2 u1 = unpack2(acc[i][1]);
                tr[to * 4 + 0][te * 4 + i] = u0.x * S;
                tr[to * 4 + 1][te * 4 + i] = u0.y * S;
                tr[to * 4 + 2][te * 4 + i] = u1.x * S;
                tr[to * 4 + 3][te * 4 + i] = u1.y * S;
            }
        }
        __syncthreads();
        for (int idx = tid; idx < 64 * 16; idx += 256) {
            int ol = idx >> 4, tl4 = (idx & 15) * 4;
            int o = o0 + ol, t = t0 + tl4;
            if (o < DO && t < DI) {
                float4 v = make_float4(tr[ol][tl4], tr[ol][tl4 + 1],
                                       tr[ol][tl4 + 2], tr[ol][tl4 + 3]);
                *(float4*)&outp[(size_t)o * DI + t] = v;
            }
        }
        __syncthreads();
    }
}

// ---------------- edge messages + scatter-add (M transposed, f32x2) ----------------
__global__ void __launch_bounds__(256) k_edge(
    const float* __restrict__ ent_emb, const int* __restrict__ src,
    const int* __restrict__ dst, const float* __restrict__ nrm) {
    extern __shared__ float xs[];  // [64][200], norm folded
    __shared__ int s_src[64];
    __shared__ int s_dst[64];
    __shared__ float s_nrm[64];
    int g = blockIdx.y;
    int base = g_off[g];
    int ng = g_off[g + 1] - base;
    int tid = threadIdx.x;
    const float* B = g_M + (size_t)g * (DI * DO);  // [o][t]
    int te = tid >> 4, to = tid & 15;
    int m0 = te * 4;

    for (int t0 = blockIdx.x * 64; t0 < ng; t0 += gridDim.x * 64) {
        int cnt = min(64, ng - t0);
        __syncthreads();
        if (tid < 64) {
            if (tid < cnt) {
                int e = g_eidx[base + t0 + tid];
                s_src[tid] = src[e];
                s_dst[tid] = dst[e];
                s_nrm[tid] = nrm[e];
            } else {
                s_src[tid] = 0;
                s_dst[tid] = 0;
                s_nrm[tid] = 0.f;
            }
        }
        __syncthreads();
        for (int idx = tid; idx < 64 * 50; idx += 256) {
            int row = idx / 50, q = idx - row * 50;
            float4 v = *(const float4*)&ent_emb[(size_t)s_src[row] * DI + q * 4];
            float nv = s_nrm[row];
            v.x *= nv; v.y *= nv; v.z *= nv; v.w *= nv;
            *(float4*)&xs[row * DI + q * 4] = v;
        }
        __syncthreads();

        for (int ot = 0; ot < 7; ++ot) {
            int n0 = ot * 64 + to * 4;
            if (n0 >= DO) continue;
            u64 acc[4][4] = {};
            for (int k = 0; k < DI; k += 4) {
                ulonglong2 a2[4], b2[4];
#pragma unroll
                for (int i = 0; i < 4; i++)
                    a2[i] = *(const ulonglong2*)&xs[(m0 + i) * DI + k];
#pragma unroll
                for (int j = 0; j < 4; j++)
                    b2[j] = *(const ulonglong2*)&B[(size_t)(n0 + j) * DI + k];
#pragma unroll
                for (int i = 0; i < 4; i++)
#pragma unroll
                    for (int j = 0; j < 4; j++) {
                        acc[i][j] = ffma2(a2[i].x, b2[j].x, acc[i][j]);
                        acc[i][j] = ffma2(a2[i].y, b2[j].y, acc[i][j]);
                    }
            }
#pragma unroll
            for (int i = 0; i < 4; i++) {
                int mm = m0 + i;
                if (mm < cnt) {
                    float r[4];
#pragma unroll
                    for (int j = 0; j < 4; j++) {
                        float2 u = unpack2(acc[i][j]);
                        r[j] = u.x + u.y;
                    }
                    red4(g_x + (size_t)s_dst[mm] * DO + n0, r[0], r[1], r[2], r[3]);
                }
            }
        }
    }
}

// ---------------- self-loop GEMM + x finalize (f32x2) ----------------
__global__ void __launch_bounds__(256) k_loopx(
    const float* __restrict__ ent_emb, const float* __restrict__ bias_w) {
    extern __shared__ float xs[];
    int row0 = blockIdx.x * 64;
    int cnt = min(64, NE - row0);
    int tid = threadIdx.x;

    for (int idx = tid; idx < 64 * 50; idx += 256) {
        int row = idx / 50, q = idx - row * 50;
        float4 v = make_float4(0.f, 0.f, 0.f, 0.f);
        if (row < cnt) v = *(const float4*)&ent_emb[(size_t)(row0 + row) * DI + q * 4];
        *(float4*)&xs[row * DI + q * 4] = v;
    }
    __syncthreads();

    int te = tid >> 4, to = tid & 15;
    int m0 = te * 4;

    for (int ot = 0; ot < 7; ++ot) {
        int n0 = ot * 64 + to * 4;
        if (n0 >= DO) continue;
        u64 acc[4][4] = {};
        for (int k = 0; k < DI; k += 4) {
            ulonglong2 a2[4], b2[4];
#pragma unroll
            for (int i = 0; i < 4; i++)
                a2[i] = *(const ulonglong2*)&xs[(m0 + i) * DI + k];
#pragma unroll
            for (int j = 0; j < 4; j++)
                b2[j] = *(const ulonglong2*)&g_Mloop[(size_t)(n0 + j) * DI + k];
#pragma unroll
            for (int i = 0; i < 4; i++)
#pragma unroll
                for (int j = 0; j < 4; j++) {
                    acc[i][j] = ffma2(a2[i].x, b2[j].x, acc[i][j]);
                    acc[i][j] = ffma2(a2[i].y, b2[j].y, acc[i][j]);
                }
        }
        float4 b4 = *(const float4*)&bias_w[n0];
#pragma unroll
        for (int i = 0; i < 4; i++) {
            int mm = m0 + i;
            if (mm < cnt) {
                float r[4];
#pragma unroll
                for (int j = 0; j < 4; j++) {
                    float2 u = unpack2(acc[i][j]);
                    r[j] = u.x + u.y;
                }
                float* xr = g_x + (size_t)(row0 + mm) * DO + n0;
                float4 cur = *(float4*)xr;
                *(float4*)xr = make_float4(cur.x + r[0] + b4.x, cur.y + r[1] + b4.y,
                                           cur.z + r[2] + b4.z, cur.w + r[3] + b4.w);
            }
        }
    }
}

// ---------------- BN column stats ----------------
__global__ void k_stats() {
    int c = threadIdx.x;  // blockDim = 400
    float s = 0.f, q = 0.f;
    for (int r = blockIdx.x; r < NE; r += gridDim.x) {
        float v = g_x[(size_t)r * DO + c];
        s += v;
        q += v * v;
    }
    atomicAdd(&g_stats[c], s);
    atomicAdd(&g_stats[DO + c], q);
}

__global__ void k_bn(const float* __restrict__ gamma, const float* __restrict__ beta) {
    int c = threadIdx.x;
    if (c < DO) {
        float mean = g_stats[c] / (float)NE;
        float var = g_stats[DO + c] / (float)NE - mean * mean;
        float sc = gamma[c] * rsqrtf(var + BN_EPS);
        g_scale[c] = sc;
        g_shift[c] = beta[c] - mean * sc;
    }
}

// ---------------- r = rel_emb @ w_rel ----------------
__global__ void k_rel(const float* __restrict__ rel_emb, const float* __restrict__ w_rel) {
    int idx = blockIdx.x * blockDim.x + threadIdx.x;
    if (idx < NR * DO) {
        int row = idx / DO, col = idx - row * DO;
        float acc = 0.f;
        for (int k = 0; k < DI; k++)
            acc = fmaf(rel_emb[row * DI + k], w_rel[k * DO + col], acc);
        g_r[idx] = acc;
    }
}

// ---------------- obj = tanh(bn(x[head])) * r[rel] ----------------
__global__ void k_obj(const int* __restrict__ triples) {
    int idx = blockIdx.x * blockDim.x + threadIdx.x;
    if (idx < NB * DO) {
        int i = idx / DO, c = idx - i * DO;
        int h = triples[3 * i], rl = triples[3 * i + 1];
        float v = tanhf(g_x[(size_t)h * DO + c] * g_scale[c] + g_shift[c]);
        g_obj[idx] = v * g_r[rl * DO + c];
    }
}

// ---------------- score = sigmoid(obj @ emb^T + bias)  (f32x2) ----------------
#define KC 80
#define KST 84
__global__ void __launch_bounds__(256) k_score(
    const float* __restrict__ emb, const float* __restrict__ ebias,
    float* __restrict__ out) {
    __shared__ float As[64 * KST];
    __shared__ float Bs[64 * KST];
    int i0 = blockIdx.x * 64;
    int e0 = blockIdx.y * 64;
    int tid = threadIdx.x;
    int te = tid >> 4, to = tid & 15;
    int m0 = te * 4, n0 = to * 4;
    u64 acc[4][4] = {};

    for (int kc = 0; kc < 5; ++kc) {
        int k0 = kc * KC;
        __syncthreads();
        for (int idx = tid; idx < 64 * 20; idx += 256) {
            int row = idx / 20, q = idx - row * 20;
            *(float4*)&As[row * KST + q * 4] =
                *(const float4*)&g_obj[(size_t)(i0 + row) * DO + k0 + q * 4];
            int e = e0 + row;
            float4 v = make_float4(0.f, 0.f, 0.f, 0.f);
            if (e < NE) v = *(const float4*)&emb[(size_t)e * DO + k0 + q * 4];
            *(float4*)&Bs[row * KST + q * 4] = v;
        }
        __syncthreads();
#pragma unroll 5
        for (int k = 0; k < KC; k += 4) {
            ulonglong2 a2[4], b2[4];
#pragma unroll
            for (int i = 0; i < 4; i++)
                a2[i] = *(const ulonglong2*)&As[(m0 + i) * KST + k];
#pragma unroll
            for (int j = 0; j < 4; j++)
                b2[j] = *(const ulonglong2*)&Bs[(n0 + j) * KST + k];
#pragma unroll
            for (int i = 0; i < 4; i++)
#pragma unroll
                for (int j = 0; j < 4; j++) {
                    acc[i][j] = ffma2(a2[i].x, b2[j].x, acc[i][j]);
                    acc[i][j] = ffma2(a2[i].y, b2[j].y, acc[i][j]);
                }
        }
    }

    bool full = (e0 + 64 <= NE);
#pragma unroll
    for (int i = 0; i < 4; i++) {
        int row = i0 + m0 + i;
        if (full) {
            float4 r4;
            float* rp = &r4.x;
#pragma unroll
            for (int j = 0; j < 4; j++) {
                float2 u = unpack2(acc[i][j]);
                float v = u.x + u.y + ebias[e0 + n0 + j];
                rp[j] = 1.f / (1.f + __expf(-v));
            }
            *(float4*)&out[(size_t)row * NE + e0 + n0] = r4;
        } else {
#pragma unroll
            for (int j = 0; j < 4; j++) {
                int e = e0 + n0 + j;
                if (e < NE) {
                    float2 u = unpack2(acc[i][j]);
                    float v = u.x + u.y + ebias[e];
                    out[(size_t)row * NE + e] = 1.f / (1.f + __expf(-v));
                }
            }
        }
    }
}

// ---------------- launch ----------------
extern "C" void kernel_launch(void* const* d_in, const int* in_sizes, int n_in,
                              void* d_out, int out_size) {
    const float* ent_emb  = (const float*)d_in[0];
    const float* rel_emb  = (const float*)d_in[1];
    const float* in_w     = (const float*)d_in[2];
    const float* out_w    = (const float*)d_in[3];
    const float* loop_w   = (const float*)d_in[4];
    const float* w_rel    = (const float*)d_in[5];
    const float* loop_rel = (const float*)d_in[6];
    const float* bias_w   = (const float*)d_in[7];
    const float* bn_gamma = (const float*)d_in[8];
    const float* bn_beta  = (const float*)d_in[9];
    const float* emb_ent  = (const float*)d_in[10];
    const float* ent_bias = (const float*)d_in[11];
    const int*   src      = (const int*)d_in[12];
    const int*   dst      = (const int*)d_in[13];
    const int*   et       = (const int*)d_in[14];
    const float* enorm    = (const float*)d_in[15];
    const int*   triples  = (const int*)d_in[16];
    float* out = (float*)d_out;

    const int SM_EDGE = 64 * DI * 4;  // 51200 bytes dynamic smem
    cudaFuncSetAttribute(k_edge, cudaFuncAttributeMaxDynamicSharedMemorySize, SM_EDGE);
    cudaFuncSetAttribute(k_loopx, cudaFuncAttributeMaxDynamicSharedMemorySize, SM_EDGE);

    k_zero<<<4096, 256>>>();
    k_hist<<<(NEDGE + 255) / 256, 256>>>(et);
    k_scan<<<1, 1024>>>();
    k_scatter<<<(NEDGE + 255) / 256, 256>>>(et);
    k_M<<<dim3(4, 801), 256>>>(rel_emb, in_w, out_w, loop_w, loop_rel);
    k_edge<<<dim3(16, NGROUP), 256, SM_EDGE>>>(ent_emb, src, dst, enorm);
    k_loopx<<<(NE + 63) / 64, 256, SM_EDGE>>>(ent_emb, bias_w);
    k_stats<<<256, 400>>>();
    k_bn<<<1, 512>>>(bn_gamma, bn_beta);
    k_rel<<<(NR * DO + 255) / 256, 256>>>(rel_emb, w_rel);
    k_obj<<<(NB * DO + 255) / 256, 256>>>(triples);
    k_score<<<dim3(NB / 64, (NE + 63) / 64), 256>>>(emb_ent, ent_bias, out);
}

// round 6
// speedup vs baseline: 2.4479x; 2.4479x over previous
#include <cuda_runtime.h>
#include <cuda_bf16.h>
#include <cstdint>
#include <math.h>

#define NE 100000
#define NR 400
#define DI 200
#define DO 400
#define NEDGE 600000
#define HALFE 300000
#define NB 1024
#define NGROUP 800
#define BN_EPS 1e-5f

#define KP 448      // K padded for score GEMM (7 x 64)

typedef unsigned long long u64;

// ---------------- device scratch ----------------
__device__ float g_M[(size_t)NGROUP * DI * DO];
__device__ float g_Mloop[DI * DO];
__device__ float g_x[(size_t)NE * DO];
__device__ float g_stats[2 * DO];
__device__ float g_scale[DO];
__device__ float g_shift[DO];
__device__ float g_r[NR * DO];
__device__ __nv_bfloat16 g_obj_hi[NB * KP];
__device__ __nv_bfloat16 g_obj_lo[NB * KP];
__device__ __nv_bfloat16 g_emb_hi[(size_t)NE * KP];
__device__ __nv_bfloat16 g_emb_lo[(size_t)NE * KP];
__device__ int   g_hist[NGROUP];
__device__ int   g_off[NGROUP + 1];
__device__ int   g_pos[NGROUP];
__device__ int   g_eidx[NEDGE];

// ---------------- helpers ----------------
__device__ __forceinline__ void red4(float* p, float a, float b, float c, float d) {
    asm volatile("red.global.add.v4.f32 [%0], {%1,%2,%3,%4};"
                 :: "l"(p), "f"(a), "f"(b), "f"(c), "f"(d) : "memory");
}
__device__ __forceinline__ uint32_t smem_u32(const void* p) {
    uint32_t a;
    asm("{ .reg .u64 t; cvta.to.shared.u64 t, %1; cvt.u32.u64 %0, t; }" : "=r"(a) : "l"(p));
    return a;
}
__device__ __forceinline__ void ldsm_x4(uint32_t* r, uint32_t a) {
    asm volatile("ldmatrix.sync.aligned.m8n8.x4.shared.b16 {%0,%1,%2,%3}, [%4];"
                 : "=r"(r[0]), "=r"(r[1]), "=r"(r[2]), "=r"(r[3]) : "r"(a));
}
__device__ __forceinline__ void ldsm_x2(uint32_t* r, uint32_t a) {
    asm volatile("ldmatrix.sync.aligned.m8n8.x2.shared.b16 {%0,%1}, [%2];"
                 : "=r"(r[0]), "=r"(r[1]) : "r"(a));
}
__device__ __forceinline__ void mma16816(float* d, const uint32_t* a, const uint32_t* b) {
    asm volatile(
        "mma.sync.aligned.m16n8k16.row.col.f32.bf16.bf16.f32 "
        "{%0,%1,%2,%3}, {%4,%5,%6,%7}, {%8,%9}, {%0,%1,%2,%3};"
        : "+f"(d[0]), "+f"(d[1]), "+f"(d[2]), "+f"(d[3])
        : "r"(a[0]), "r"(a[1]), "r"(a[2]), "r"(a[3]), "r"(b[0]), "r"(b[1]));
}

// ---------------- zero scratch ----------------
__global__ void k_zero() {
    const size_t n4 = (size_t)NE * DO / 4;
    float4* p = reinterpret_cast<float4*>(g_x);
    const float4 z = make_float4(0.f, 0.f, 0.f, 0.f);
    for (size_t i = (size_t)blockIdx.x * blockDim.x + threadIdx.x; i < n4;
         i += (size_t)gridDim.x * blockDim.x)
        p[i] = z;
    int gid = blockIdx.x * blockDim.x + threadIdx.x;
    if (gid < NGROUP) g_hist[gid] = 0;
    if (gid < 2 * DO) g_stats[gid] = 0.f;
}

// ---------------- edge grouping ----------------
__global__ void k_hist(const int* __restrict__ et) {
    int e = blockIdx.x * blockDim.x + threadIdx.x;
    if (e < NEDGE) atomicAdd(&g_hist[et[e] + (e < HALFE ? 0 : 400)], 1);
}

__global__ void k_scan() {
    __shared__ int s[NGROUP];
    int i = threadIdx.x;
    if (i < NGROUP) s[i] = g_hist[i];
    __syncthreads();
    for (int d = 1; d < NGROUP; d <<= 1) {
        int v = 0;
        if (i < NGROUP && i >= d) v = s[i - d];
        __syncthreads();
        if (i < NGROUP && i >= d) s[i] += v;
        __syncthreads();
    }
    if (i < NGROUP) {
        int excl = s[i] - g_hist[i];
        g_off[i] = excl;
        g_pos[i] = excl;
        if (i == NGROUP - 1) g_off[NGROUP] = s[i];
    }
}

__global__ void k_scatter(const int* __restrict__ et) {
    int e = blockIdx.x * blockDim.x + threadIdx.x;
    if (e < NEDGE) {
        int p = atomicAdd(&g_pos[et[e] + (e < HALFE ? 0 : 400)], 1);
        g_eidx[p] = e;
    }
}

// ---------------- M precompute: M[t,o] = (1/3) sum_j b[(t+j)%200] W[j,o] ----------------
__global__ void __launch_bounds__(256) k_M(
    const float* __restrict__ rel_emb, const float* __restrict__ in_w,
    const float* __restrict__ out_w, const float* __restrict__ loop_w,
    const float* __restrict__ loop_rel) {
    __shared__ float bb[464];
    int m = blockIdx.y;
    const float* bsrc;
    const float* W;
    float* outp;
    if (m < 800) {
        int h = m / 400, r = m - h * 400;
        bsrc = rel_emb + (size_t)r * DI;
        W = h ? out_w : in_w;
        outp = g_M + (size_t)m * (DI * DO);
    } else {
        bsrc = loop_rel;
        W = loop_w;
        outp = g_Mloop;
    }
    int tid = threadIdx.x;
    for (int s = tid; s < 464; s += 256) bb[s] = bsrc[s % DI];
    __syncthreads();

    int te = tid >> 4, to = tid & 15;
    int t0 = blockIdx.x * 64 + te * 4;
    const float S = 1.f / 3.f;

    for (int ot = 0; ot < 7; ++ot) {
        int n0 = ot * 64 + to * 4;
        if (n0 >= DO) continue;
        float acc[4][4] = {};
        for (int k = 0; k < DI; k += 4) {
            float aa[4][4], bv[4][4];
#pragma unroll
            for (int i = 0; i < 4; i++)
#pragma unroll
                for (int kk = 0; kk < 4; kk++)
                    aa[i][kk] = bb[t0 + i + k + kk];
#pragma unroll
            for (int kk = 0; kk < 4; kk++) {
                float4 t = *(const float4*)&W[(size_t)(k + kk) * DO + n0];
                bv[kk][0] = t.x; bv[kk][1] = t.y; bv[kk][2] = t.z; bv[kk][3] = t.w;
            }
#pragma unroll
            for (int i = 0; i < 4; i++)
#pragma unroll
                for (int j = 0; j < 4; j++)
#pragma unroll
                    for (int kk = 0; kk < 4; kk++)
                        acc[i][j] = fmaf(aa[i][kk], bv[kk][j], acc[i][j]);
        }
#pragma unroll
        for (int i = 0; i < 4; i++) {
            int row = t0 + i;
            if (row < DI)
                *(float4*)&outp[(size_t)row * DO + n0] =
                    make_float4(acc[i][0] * S, acc[i][1] * S, acc[i][2] * S, acc[i][3] * S);
        }
    }
}

// ---------------- edge messages + scatter-add ----------------
__global__ void __launch_bounds__(256) k_edge(
    const float* __restrict__ ent_emb, const int* __restrict__ src,
    const int* __restrict__ dst, const float* __restrict__ nrm) {
    extern __shared__ float xs[];
    __shared__ int s_src[64];
    __shared__ int s_dst[64];
    __shared__ float s_nrm[64];
    int g = blockIdx.y;
    int base = g_off[g];
    int ng = g_off[g + 1] - base;
    int tid = threadIdx.x;
    const float* B = g_M + (size_t)g * (DI * DO);
    int te = tid >> 4, to = tid & 15;
    int m0 = te * 4;

    for (int t0 = blockIdx.x * 64; t0 < ng; t0 += gridDim.x * 64) {
        int cnt = min(64, ng - t0);
        __syncthreads();
        if (tid < 64) {
            if (tid < cnt) {
                int e = g_eidx[base + t0 + tid];
                s_src[tid] = src[e];
                s_dst[tid] = dst[e];
                s_nrm[tid] = nrm[e];
            } else {
                s_src[tid] = 0;
                s_dst[tid] = 0;
                s_nrm[tid] = 0.f;
            }
        }
        __syncthreads();
        for (int idx = tid; idx < 64 * 50; idx += 256) {
            int row = idx / 50, q = idx - row * 50;
            float4 v = *(const float4*)&ent_emb[(size_t)s_src[row] * DI + q * 4];
            float nv = s_nrm[row];
            v.x *= nv; v.y *= nv; v.z *= nv; v.w *= nv;
            *(float4*)&xs[row * DI + q * 4] = v;
        }
        __syncthreads();

        for (int ot = 0; ot < 7; ++ot) {
            int n0 = ot * 64 + to * 4;
            if (n0 >= DO) continue;
            float acc[4][4] = {};
            for (int k = 0; k < DI; k += 4) {
                float aa[4][4], bv[4][4];
#pragma unroll
                for (int i = 0; i < 4; i++) {
                    float4 t = *(const float4*)&xs[(m0 + i) * DI + k];
                    aa[i][0] = t.x; aa[i][1] = t.y; aa[i][2] = t.z; aa[i][3] = t.w;
                }
#pragma unroll
                for (int kk = 0; kk < 4; kk++) {
                    float4 t = *(const float4*)&B[(size_t)(k + kk) * DO + n0];
                    bv[kk][0] = t.x; bv[kk][1] = t.y; bv[kk][2] = t.z; bv[kk][3] = t.w;
                }
#pragma unroll
                for (int i = 0; i < 4; i++)
#pragma unroll
                    for (int j = 0; j < 4; j++)
#pragma unroll
                        for (int kk = 0; kk < 4; kk++)
                            acc[i][j] = fmaf(aa[i][kk], bv[kk][j], acc[i][j]);
            }
#pragma unroll
            for (int i = 0; i < 4; i++) {
                int mm = m0 + i;
                if (mm < cnt)
                    red4(g_x + (size_t)s_dst[mm] * DO + n0,
                         acc[i][0], acc[i][1], acc[i][2], acc[i][3]);
            }
        }
    }
}

// ---------------- self-loop GEMM + x finalize ----------------
__global__ void __launch_bounds__(256) k_loopx(
    const float* __restrict__ ent_emb, const float* __restrict__ bias_w) {
    extern __shared__ float xs[];
    int row0 = blockIdx.x * 64;
    int cnt = min(64, NE - row0);
    int tid = threadIdx.x;

    for (int idx = tid; idx < 64 * 50; idx += 256) {
        int row = idx / 50, q = idx - row * 50;
        float4 v = make_float4(0.f, 0.f, 0.f, 0.f);
        if (row < cnt) v = *(const float4*)&ent_emb[(size_t)(row0 + row) * DI + q * 4];
        *(float4*)&xs[row * DI + q * 4] = v;
    }
    __syncthreads();

    int te = tid >> 4, to = tid & 15;
    int m0 = te * 4;

    for (int ot = 0; ot < 7; ++ot) {
        int n0 = ot * 64 + to * 4;
        if (n0 >= DO) continue;
        float acc[4][4] = {};
        for (int k = 0; k < DI; k += 4) {
            float aa[4][4], bv[4][4];
#pragma unroll
            for (int i = 0; i < 4; i++) {
                float4 t = *(const float4*)&xs[(m0 + i) * DI + k];
                aa[i][0] = t.x; aa[i][1] = t.y; aa[i][2] = t.z; aa[i][3] = t.w;
            }
#pragma unroll
            for (int kk = 0; kk < 4; kk++) {
                float4 t = *(const float4*)&g_Mloop[(size_t)(k + kk) * DO + n0];
                bv[kk][0] = t.x; bv[kk][1] = t.y; bv[kk][2] = t.z; bv[kk][3] = t.w;
            }
#pragma unroll
            for (int i = 0; i < 4; i++)
#pragma unroll
                for (int j = 0; j < 4; j++)
#pragma unroll
                    for (int kk = 0; kk < 4; kk++)
                        acc[i][j] = fmaf(aa[i][kk], bv[kk][j], acc[i][j]);
        }
        float4 b4 = *(const float4*)&bias_w[n0];
#pragma unroll
        for (int i = 0; i < 4; i++) {
            int mm = m0 + i;
            if (mm < cnt) {
                float* xr = g_x + (size_t)(row0 + mm) * DO + n0;
                float4 cur = *(float4*)xr;
                *(float4*)xr = make_float4(cur.x + acc[i][0] + b4.x, cur.y + acc[i][1] + b4.y,
                                           cur.z + acc[i][2] + b4.z, cur.w + acc[i][3] + b4.w);
            }
        }
    }
}

// ---------------- BN column stats ----------------
__global__ void k_stats() {
    int c = threadIdx.x;
    float s = 0.f, q = 0.f;
    for (int r = blockIdx.x; r < NE; r += gridDim.x) {
        float v = g_x[(size_t)r * DO + c];
        s += v;
        q += v * v;
    }
    atomicAdd(&g_stats[c], s);
    atomicAdd(&g_stats[DO + c], q);
}

__global__ void k_bn(const float* __restrict__ gamma, const float* __restrict__ beta) {
    int c = threadIdx.x;
    if (c < DO) {
        float mean = g_stats[c] / (float)NE;
        float var = g_stats[DO + c] / (float)NE - mean * mean;
        float sc = gamma[c] * rsqrtf(var + BN_EPS);
        g_scale[c] = sc;
        g_shift[c] = beta[c] - mean * sc;
    }
}

// ---------------- r = rel_emb @ w_rel ----------------
__global__ void k_rel(const float* __restrict__ rel_emb, const float* __restrict__ w_rel) {
    int idx = blockIdx.x * blockDim.x + threadIdx.x;
    if (idx < NR * DO) {
        int row = idx / DO, col = idx - row * DO;
        float acc = 0.f;
        for (int k = 0; k < DI; k++)
            acc = fmaf(rel_emb[row * DI + k], w_rel[k * DO + col], acc);
        g_r[idx] = acc;
    }
}

// ---------------- obj = tanh(bn(x[head])) * r[rel] -> bf16 hi/lo ----------------
__global__ void k_obj(const int* __restrict__ triples) {
    int i = blockIdx.x;   // grid NB, block KP
    int c = threadIdx.x;
    float v = 0.f;
    if (c < DO) {
        int h = triples[3 * i], rl = triples[3 * i + 1];
        float t = tanhf(g_x[(size_t)h * DO + c] * g_scale[c] + g_shift[c]);
        v = t * g_r[rl * DO + c];
    }
    __nv_bfloat16 hi = __float2bfloat16(v);
    g_obj_hi[i * KP + c] = hi;
    g_obj_lo[i * KP + c] = __float2bfloat16(v - __bfloat162float(hi));
}

// ---------------- emb -> bf16 hi/lo, padded to KP ----------------
__global__ void k_split_emb(const float* __restrict__ emb) {
    int row = blockIdx.x;   // grid NE, block KP
    int c = threadIdx.x;
    float v = (c < DO) ? emb[(size_t)row * DO + c] : 0.f;
    __nv_bfloat16 hi = __float2bfloat16(v);
    size_t idx = (size_t)row * KP + c;
    g_emb_hi[idx] = hi;
    g_emb_lo[idx] = __float2bfloat16(v - __bfloat162float(hi));
}

// ---------------- score via mma.sync (bf16 3-term split, fp32 accum) ----------------
// block 256 = 8 warps (2m x 4n). Block tile 128x128, warp tile 64x32.
// smem: 4 planes of [128][72] bf16, stride 144B (conflict-free ldmatrix).
#define SSTR 144
#define PLANE (128 * SSTR)
__global__ void __launch_bounds__(256) k_score_mma(
    const float* __restrict__ ebias, float* __restrict__ out) {
    extern __shared__ char sm[];
    uint32_t sbase = smem_u32(sm);
    const uint32_t A_HI = 0, A_LO = PLANE, B_HI = 2 * PLANE, B_LO = 3 * PLANE;

    int tid = threadIdx.x, wid = tid >> 5, lane = tid & 31;
    int wm = wid >> 2, wn = wid & 3;
    int i0 = blockIdx.x * 128;
    int e0 = blockIdx.y * 128;
    int g = lane >> 2, tg = lane & 3;

    // lane-dependent ldmatrix offsets
    int mat = lane >> 3, r = lane & 7;
    uint32_t aoff = (uint32_t)(((mat & 1) * 8 + r) * SSTR + (mat >> 1) * 16);
    uint32_t boff = (uint32_t)(r * SSTR + ((lane >> 3) & 1) * 16);

    float acc[4][4][4] = {};

    for (int ch = 0; ch < 7; ch++) {
        int k0 = ch * 64;
        __syncthreads();
        const uint4 z4 = make_uint4(0, 0, 0, 0);
        for (int idx = tid; idx < 128 * 8; idx += 256) {
            int row = idx >> 3, seg = idx & 7;
            uint32_t so = (uint32_t)(row * SSTR + seg * 16);
            *(uint4*)(sm + A_HI + so) =
                *(const uint4*)&g_obj_hi[(size_t)(i0 + row) * KP + k0 + seg * 8];
            *(uint4*)(sm + A_LO + so) =
                *(const uint4*)&g_obj_lo[(size_t)(i0 + row) * KP + k0 + seg * 8];
            int e = e0 + row;
            uint4 vh = z4, vl = z4;
            if (e < NE) {
                vh = *(const uint4*)&g_emb_hi[(size_t)e * KP + k0 + seg * 8];
                vl = *(const uint4*)&g_emb_lo[(size_t)e * KP + k0 + seg * 8];
            }
            *(uint4*)(sm + B_HI + so) = vh;
            *(uint4*)(sm + B_LO + so) = vl;
        }
        __syncthreads();

#pragma unroll
        for (int ks = 0; ks < 4; ks++) {
            uint32_t ah[4][4], al[4][4], bh[4][2], bl[4][2];
#pragma unroll
            for (int mt = 0; mt < 4; mt++) {
                uint32_t ab = (uint32_t)((wm * 64 + mt * 16) * SSTR + ks * 32) + aoff;
                ldsm_x4(ah[mt], sbase + A_HI + ab);
                ldsm_x4(al[mt], sbase + A_LO + ab);
            }
#pragma unroll
            for (int nt = 0; nt < 4; nt++) {
                uint32_t bb = (uint32_t)((wn * 32 + nt * 8) * SSTR + ks * 32) + boff;
                ldsm_x2(bh[nt], sbase + B_HI + bb);
                ldsm_x2(bl[nt], sbase + B_LO + bb);
            }
#pragma unroll
            for (int mt = 0; mt < 4; mt++)
#pragma unroll
                for (int nt = 0; nt < 4; nt++) {
                    mma16816(acc[mt][nt], ah[mt], bh[nt]);
                    mma16816(acc[mt][nt], ah[mt], bl[nt]);
                    mma16816(acc[mt][nt], al[mt], bh[nt]);
                }
        }
    }

    // epilogue: bias + sigmoid, float2 stores
#pragma unroll
    for (int mt = 0; mt < 4; mt++) {
        int row = i0 + wm * 64 + mt * 16 + g;
#pragma unroll
        for (int nt = 0; nt < 4; nt++) {
            int col = e0 + wn * 32 + nt * 8 + tg * 2;
            if (col < NE) {
                float b0 = ebias[col], b1 = ebias[col + 1];
                float2 v0;
                v0.x = 1.f / (1.f + __expf(-(acc[mt][nt][0] + b0)));
                v0.y = 1.f / (1.f + __expf(-(acc[mt][nt][1] + b1)));
                *(float2*)&out[(size_t)row * NE + col] = v0;
                float2 v1;
                v1.x = 1.f / (1.f + __expf(-(acc[mt][nt][2] + b0)));
                v1.y = 1.f / (1.f + __expf(-(acc[mt][nt][3] + b1)));
                *(float2*)&out[(size_t)(row + 8) * NE + col] = v1;
            }
        }
    }
}

// ---------------- launch ----------------
extern "C" void kernel_launch(void* const* d_in, const int* in_sizes, int n_in,
                              void* d_out, int out_size) {
    const float* ent_emb  = (const float*)d_in[0];
    const float* rel_emb  = (const float*)d_in[1];
    const float* in_w     = (const float*)d_in[2];
    const float* out_w    = (const float*)d_in[3];
    const float* loop_w   = (const float*)d_in[4];
    const float* w_rel    = (const float*)d_in[5];
    const float* loop_rel = (const float*)d_in[6];
    const float* bias_w   = (const float*)d_in[7];
    const float* bn_gamma = (const float*)d_in[8];
    const float* bn_beta  = (const float*)d_in[9];
    const float* emb_ent  = (const float*)d_in[10];
    const float* ent_bias = (const float*)d_in[11];
    const int*   src      = (const int*)d_in[12];
    const int*   dst      = (const int*)d_in[13];
    const int*   et       = (const int*)d_in[14];
    const float* enorm    = (const float*)d_in[15];
    const int*   triples  = (const int*)d_in[16];
    float* out = (float*)d_out;

    const int SM_EDGE = 64 * DI * 4;
    cudaFuncSetAttribute(k_edge, cudaFuncAttributeMaxDynamicSharedMemorySize, SM_EDGE);
    cudaFuncSetAttribute(k_loopx, cudaFuncAttributeMaxDynamicSharedMemorySize, SM_EDGE);
    const int SM_SCORE = 4 * PLANE;  // 73728
    cudaFuncSetAttribute(k_score_mma, cudaFuncAttributeMaxDynamicSharedMemorySize, SM_SCORE);

    k_zero<<<4096, 256>>>();
    k_hist<<<(NEDGE + 255) / 256, 256>>>(et);
    k_scan<<<1, 1024>>>();
    k_scatter<<<(NEDGE + 255) / 256, 256>>>(et);
    k_M<<<dim3(4, 801), 256>>>(rel_emb, in_w, out_w, loop_w, loop_rel);
    k_split_emb<<<NE, KP>>>(emb_ent);
    k_edge<<<dim3(16, NGROUP), 256, SM_EDGE>>>(ent_emb, src, dst, enorm);
    k_loopx<<<(NE + 63) / 64, 256, SM_EDGE>>>(ent_emb, bias_w);
    k_stats<<<256, 400>>>();
    k_bn<<<1, 512>>>(bn_gamma, bn_beta);
    k_rel<<<(NR * DO + 255) / 256, 256>>>(rel_emb, w_rel);
    k_obj<<<NB, KP>>>(triples);
    k_score_mma<<<dim3(NB / 128, (NE + 127) / 128), 256, SM_SCORE>>>(ent_bias, out);
}

// round 7
// speedup vs baseline: 3.1505x; 1.2870x over previous
#include <cuda_runtime.h>
#include <cuda_bf16.h>
#include <cstdint>
#include <math.h>

#define NE 100000
#define NR 400
#define DI 200
#define DO 400
#define NEDGE 600000
#define HALFE 300000
#define NB 1024
#define NGROUP 800
#define BN_EPS 1e-5f

#define KP 448      // K padded for score GEMM
#define EN 448      // padded output cols for edge GEMM (14 n-tiles x 8 x 4 warps / ... 4x112)
#define EK 208      // padded K for edge GEMM (13 x 16)

typedef unsigned long long u64;

// ---------------- device scratch ----------------
__device__ float g_M[(size_t)NGROUP * DI * DO];   // fp32 [t][o] per group
__device__ float g_Mloop[DI * DO];
__device__ __nv_bfloat16 g_Mbh[(size_t)NGROUP * EN * EK];  // bf16 hi [o_perm][t]
__device__ __nv_bfloat16 g_Mbl[(size_t)NGROUP * EN * EK];  // bf16 lo
__device__ float g_x[(size_t)NE * DO];
__device__ float g_stats[2 * DO];
__device__ float g_scale[DO];
__device__ float g_shift[DO];
__device__ float g_r[NR * DO];
__device__ __nv_bfloat16 g_obj_hi[NB * KP];
__device__ __nv_bfloat16 g_obj_lo[NB * KP];
__device__ __nv_bfloat16 g_emb_hi[(size_t)NE * KP];
__device__ __nv_bfloat16 g_emb_lo[(size_t)NE * KP];
__device__ int   g_hist[NGROUP];
__device__ int   g_off[NGROUP + 1];
__device__ int   g_pos[NGROUP];
__device__ int   g_eidx[NEDGE];

// ---------------- helpers ----------------
__device__ __forceinline__ void red4(float* p, float a, float b, float c, float d) {
    asm volatile("red.global.add.v4.f32 [%0], {%1,%2,%3,%4};"
                 :: "l"(p), "f"(a), "f"(b), "f"(c), "f"(d) : "memory");
}
__device__ __forceinline__ uint32_t smem_u32(const void* p) {
    uint32_t a;
    asm("{ .reg .u64 t; cvta.to.shared.u64 t, %1; cvt.u32.u64 %0, t; }" : "=r"(a) : "l"(p));
    return a;
}
__device__ __forceinline__ void ldsm_x4(uint32_t* r, uint32_t a) {
    asm volatile("ldmatrix.sync.aligned.m8n8.x4.shared.b16 {%0,%1,%2,%3}, [%4];"
                 : "=r"(r[0]), "=r"(r[1]), "=r"(r[2]), "=r"(r[3]) : "r"(a));
}
__device__ __forceinline__ void ldsm_x2(uint32_t* r, uint32_t a) {
    asm volatile("ldmatrix.sync.aligned.m8n8.x2.shared.b16 {%0,%1}, [%2];"
                 : "=r"(r[0]), "=r"(r[1]) : "r"(a));
}
__device__ __forceinline__ void mma16816(float* d, const uint32_t* a, const uint32_t* b) {
    asm volatile(
        "mma.sync.aligned.m16n8k16.row.col.f32.bf16.bf16.f32 "
        "{%0,%1,%2,%3}, {%4,%5,%6,%7}, {%8,%9}, {%0,%1,%2,%3};"
        : "+f"(d[0]), "+f"(d[1]), "+f"(d[2]), "+f"(d[3])
        : "r"(a[0]), "r"(a[1]), "r"(a[2]), "r"(a[3]), "r"(b[0]), "r"(b[1]));
}

// ---------------- zero scratch ----------------
__global__ void k_zero() {
    const size_t n4 = (size_t)NE * DO / 4;
    float4* p = reinterpret_cast<float4*>(g_x);
    const float4 z = make_float4(0.f, 0.f, 0.f, 0.f);
    for (size_t i = (size_t)blockIdx.x * blockDim.x + threadIdx.x; i < n4;
         i += (size_t)gridDim.x * blockDim.x)
        p[i] = z;
    int gid = blockIdx.x * blockDim.x + threadIdx.x;
    if (gid < NGROUP) g_hist[gid] = 0;
    if (gid < 2 * DO) g_stats[gid] = 0.f;
}

// ---------------- edge grouping ----------------
__global__ void k_hist(const int* __restrict__ et) {
    int e = blockIdx.x * blockDim.x + threadIdx.x;
    if (e < NEDGE) atomicAdd(&g_hist[et[e] + (e < HALFE ? 0 : 400)], 1);
}

__global__ void k_scan() {
    __shared__ int s[NGROUP];
    int i = threadIdx.x;
    if (i < NGROUP) s[i] = g_hist[i];
    __syncthreads();
    for (int d = 1; d < NGROUP; d <<= 1) {
        int v = 0;
        if (i < NGROUP && i >= d) v = s[i - d];
        __syncthreads();
        if (i < NGROUP && i >= d) s[i] += v;
        __syncthreads();
    }
    if (i < NGROUP) {
        int excl = s[i] - g_hist[i];
        g_off[i] = excl;
        g_pos[i] = excl;
        if (i == NGROUP - 1) g_off[NGROUP] = s[i];
    }
}

__global__ void k_scatter(const int* __restrict__ et) {
    int e = blockIdx.x * blockDim.x + threadIdx.x;
    if (e < NEDGE) {
        int p = atomicAdd(&g_pos[et[e] + (e < HALFE ? 0 : 400)], 1);
        g_eidx[p] = e;
    }
}

// ---------------- M precompute (fp32): M[t,o] = (1/3) sum_j b[(t+j)%200] W[j,o] ----------------
__global__ void __launch_bounds__(256) k_M(
    const float* __restrict__ rel_emb, const float* __restrict__ in_w,
    const float* __restrict__ out_w, const float* __restrict__ loop_w,
    const float* __restrict__ loop_rel) {
    __shared__ float bb[464];
    int m = blockIdx.y;
    const float* bsrc;
    const float* W;
    float* outp;
    if (m < 800) {
        int h = m / 400, r = m - h * 400;
        bsrc = rel_emb + (size_t)r * DI;
        W = h ? out_w : in_w;
        outp = g_M + (size_t)m * (DI * DO);
    } else {
        bsrc = loop_rel;
        W = loop_w;
        outp = g_Mloop;
    }
    int tid = threadIdx.x;
    for (int s = tid; s < 464; s += 256) bb[s] = bsrc[s % DI];
    __syncthreads();

    int te = tid >> 4, to = tid & 15;
    int t0 = blockIdx.x * 64 + te * 4;
    const float S = 1.f / 3.f;

    for (int ot = 0; ot < 7; ++ot) {
        int n0 = ot * 64 + to * 4;
        if (n0 >= DO) continue;
        float acc[4][4] = {};
        for (int k = 0; k < DI; k += 4) {
            float aa[4][4], bv[4][4];
#pragma unroll
            for (int i = 0; i < 4; i++)
#pragma unroll
                for (int kk = 0; kk < 4; kk++)
                    aa[i][kk] = bb[t0 + i + k + kk];
#pragma unroll
            for (int kk = 0; kk < 4; kk++) {
                float4 t = *(const float4*)&W[(size_t)(k + kk) * DO + n0];
                bv[kk][0] = t.x; bv[kk][1] = t.y; bv[kk][2] = t.z; bv[kk][3] = t.w;
            }
#pragma unroll
            for (int i = 0; i < 4; i++)
#pragma unroll
                for (int j = 0; j < 4; j++)
#pragma unroll
                    for (int kk = 0; kk < 4; kk++)
                        acc[i][j] = fmaf(aa[i][kk], bv[kk][j], acc[i][j]);
        }
#pragma unroll
        for (int i = 0; i < 4; i++) {
            int row = t0 + i;
            if (row < DI)
                *(float4*)&outp[(size_t)row * DO + n0] =
                    make_float4(acc[i][0] * S, acc[i][1] * S, acc[i][2] * S, acc[i][3] * S);
        }
    }
}

// ---------------- transpose + bf16 split of M: fp32 [t][o] -> hi/lo [o_perm][t] ----------------
// permutation within each 16-col group so epilogue lanes own 4 contiguous cols
__global__ void k_splitM() {
    __shared__ float ts[32][33];
    int g = blockIdx.y;
    int ox = blockIdx.x % 14, tt = blockIdx.x / 14;
    int o0 = ox * 32, t0 = tt * 32;
    int lx = threadIdx.x & 31, ly = threadIdx.x >> 5;
    const float* Msrc = g_M + (size_t)g * DI * DO;
#pragma unroll
    for (int i = 0; i < 4; i++) {
        int t = t0 + ly + i * 8, o = o0 + lx;
        float v = (t < DI && o < DO) ? Msrc[(size_t)t * DO + o] : 0.f;
        ts[ly + i * 8][lx] = v;
    }
    __syncthreads();
#pragma unroll
    for (int i = 0; i < 4; i++) {
        int o = o0 + ly + i * 8, t = t0 + lx;
        if (t < EK) {
            float v = ts[lx][ly + i * 8];
            int m = o & 15;
            int pm = ((m & 2) << 2) | ((m & 12) >> 1) | (m & 1);
            int op = (o & ~15) | pm;
            __nv_bfloat16 h = __float2bfloat16(v);
            size_t off = ((size_t)g * EN + op) * EK + t;
            g_Mbh[off] = h;
            g_Mbl[off] = __float2bfloat16(v - __bfloat162float(h));
        }
    }
}

// ---------------- edge messages via mma.sync + red4 scatter ----------------
// block: 64 edges x 448 cols x K208. 8 warps 2m x 4n (warp 32 x 112).
#define ASTR 432                     // A row stride bytes (208*2 + 16)
#define BSTR 48                      // B chunk row stride bytes (32 + 16)
#define A_BYTES (64 * ASTR)          // 27648
#define B_BYTES (EN * BSTR)          // 21504
#define EDGE_SMEM (2 * A_BYTES + 2 * B_BYTES)  // 98304

__global__ void __launch_bounds__(256) k_edge_mma(
    const float* __restrict__ ent_emb, const int* __restrict__ src,
    const int* __restrict__ dst, const float* __restrict__ nrm) {
    extern __shared__ char sm[];
    uint32_t sbase = smem_u32(sm);
    const uint32_t A_HI = 0, A_LO = A_BYTES, B_HI = 2 * A_BYTES, B_LO = 2 * A_BYTES + B_BYTES;
    __shared__ int s_src[64];
    __shared__ int s_dst[64];
    __shared__ float s_nrm[64];

    int g = blockIdx.y;
    int base = g_off[g];
    int ng = g_off[g + 1] - base;
    int tid = threadIdx.x, wid = tid >> 5, lane = tid & 31;
    int wm = wid >> 2, wn = wid & 3;
    int gq = lane >> 2, tg = lane & 3;
    int mat = lane >> 3, r = lane & 7;
    uint32_t aoff = (uint32_t)(((mat & 1) * 8 + r) * ASTR + (mat >> 1) * 16);
    uint32_t boff = (uint32_t)(r * BSTR + ((lane >> 3) & 1) * 16);
    const __nv_bfloat16* Bh = g_Mbh + (size_t)g * EN * EK;
    const __nv_bfloat16* Bl = g_Mbl + (size_t)g * EN * EK;

    for (int t0 = blockIdx.x * 64; t0 < ng; t0 += gridDim.x * 64) {
        int cnt = min(64, ng - t0);
        __syncthreads();  // protect s_* and A smem from previous tile's consumers
        if (tid < 64) {
            if (tid < cnt) {
                int e = g_eidx[base + t0 + tid];
                s_src[tid] = src[e];
                s_dst[tid] = dst[e];
                s_nrm[tid] = nrm[e];
            } else {
                s_src[tid] = 0;
                s_dst[tid] = 0;
                s_nrm[tid] = 0.f;
            }
        }
        __syncthreads();
        // gather + hi/lo split: 64 rows x 26 segs of 8 bf16 (200 real + 8 pad)
        for (int idx = tid; idx < 64 * 26; idx += 256) {
            int row = idx / 26, seg = idx - row * 26;
            uint32_t hi4[4] = {0, 0, 0, 0}, lo4[4] = {0, 0, 0, 0};
            if (seg < 25) {
                const float* p = &ent_emb[(size_t)s_src[row] * DI + seg * 8];
                float nv = s_nrm[row];
#pragma unroll
                for (int q = 0; q < 4; q++) {
                    float v0 = p[q * 2] * nv, v1 = p[q * 2 + 1] * nv;
                    __nv_bfloat16 h0 = __float2bfloat16(v0), h1 = __float2bfloat16(v1);
                    __nv_bfloat16 l0 = __float2bfloat16(v0 - __bfloat162float(h0));
                    __nv_bfloat16 l1 = __float2bfloat16(v1 - __bfloat162float(h1));
                    hi4[q] = (uint32_t)__bfloat16_as_ushort(h0) |
                             ((uint32_t)__bfloat16_as_ushort(h1) << 16);
                    lo4[q] = (uint32_t)__bfloat16_as_ushort(l0) |
                             ((uint32_t)__bfloat16_as_ushort(l1) << 16);
                }
            }
            uint32_t so = (uint32_t)(row * ASTR + seg * 16);
            *(uint4*)(sm + A_HI + so) = make_uint4(hi4[0], hi4[1], hi4[2], hi4[3]);
            *(uint4*)(sm + A_LO + so) = make_uint4(lo4[0], lo4[1], lo4[2], lo4[3]);
        }

        float acc[2][14][4];
#pragma unroll
        for (int mt = 0; mt < 2; mt++)
#pragma unroll
            for (int nt = 0; nt < 14; nt++)
#pragma unroll
                for (int q = 0; q < 4; q++) acc[mt][nt][q] = 0.f;

        for (int kc = 0; kc < 13; kc++) {
            __syncthreads();  // previous chunk consumed (also covers A gather on kc=0)
            // stage B chunk: EN rows x 32B, both planes
            for (int idx = tid; idx < EN * 2; idx += 256) {
                int o = idx >> 1, half = idx & 1;
                size_t goff = (size_t)o * EK + kc * 16 + half * 8;
                *(uint4*)(sm + B_HI + o * BSTR + half * 16) = *(const uint4*)&Bh[goff];
                *(uint4*)(sm + B_LO + o * BSTR + half * 16) = *(const uint4*)&Bl[goff];
            }
            __syncthreads();
            uint32_t ah[2][4], al[2][4];
#pragma unroll
            for (int mt = 0; mt < 2; mt++) {
                uint32_t ab = (uint32_t)((wm * 32 + mt * 16) * ASTR + kc * 32) + aoff;
                ldsm_x4(ah[mt], sbase + A_HI + ab);
                ldsm_x4(al[mt], sbase + A_LO + ab);
            }
#pragma unroll
            for (int nt = 0; nt < 14; nt++) {
                uint32_t bh[2], bl[2];
                uint32_t bb = (uint32_t)((wn * 112 + nt * 8) * BSTR) + boff;
                ldsm_x2(bh, sbase + B_HI + bb);
                ldsm_x2(bl, sbase + B_LO + bb);
#pragma unroll
                for (int mt = 0; mt < 2; mt++) {
                    mma16816(acc[mt][nt], ah[mt], bh);
                    mma16816(acc[mt][nt], ah[mt], bl);
                    mma16816(acc[mt][nt], al[mt], bh);
                }
            }
        }

        // epilogue: permuted tile-pairs give 4 contiguous cols per lane -> red4
#pragma unroll
        for (int mt = 0; mt < 2; mt++) {
            int er0 = wm * 32 + mt * 16 + gq;
            int er1 = er0 + 8;
#pragma unroll
            for (int qt = 0; qt < 7; qt++) {
                int c = wn * 112 + qt * 16 + tg * 4;
                if (c < DO) {
                    float* a0 = acc[mt][2 * qt];
                    float* a1 = acc[mt][2 * qt + 1];
                    if (er0 < cnt)
                        red4(&g_x[(size_t)s_dst[er0] * DO + c], a0[0], a0[1], a1[0], a1[1]);
                    if (er1 < cnt)
                        red4(&g_x[(size_t)s_dst[er1] * DO + c], a0[2], a0[3], a1[2], a1[3]);
                }
            }
        }
    }
}

// ---------------- self-loop GEMM + x finalize (fp32 FFMA) ----------------
__global__ void __launch_bounds__(256) k_loopx(
    const float* __restrict__ ent_emb, const float* __restrict__ bias_w) {
    extern __shared__ float xs[];
    int row0 = blockIdx.x * 64;
    int cnt = min(64, NE - row0);
    int tid = threadIdx.x;

    for (int idx = tid; idx < 64 * 50; idx += 256) {
        int row = idx / 50, q = idx - row * 50;
        float4 v = make_float4(0.f, 0.f, 0.f, 0.f);
        if (row < cnt) v = *(const float4*)&ent_emb[(size_t)(row0 + row) * DI + q * 4];
        *(float4*)&xs[row * DI + q * 4] = v;
    }
    __syncthreads();

    int te = tid >> 4, to = tid & 15;
    int m0 = te * 4;

    for (int ot = 0; ot < 7; ++ot) {
        int n0 = ot * 64 + to * 4;
        if (n0 >= DO) continue;
        float acc[4][4] = {};
        for (int k = 0; k < DI; k += 4) {
            float aa[4][4], bv[4][4];
#pragma unroll
            for (int i = 0; i < 4; i++) {
                float4 t = *(const float4*)&xs[(m0 + i) * DI + k];
                aa[i][0] = t.x; aa[i][1] = t.y; aa[i][2] = t.z; aa[i][3] = t.w;
            }
#pragma unroll
            for (int kk = 0; kk < 4; kk++) {
                float4 t = *(const float4*)&g_Mloop[(size_t)(k + kk) * DO + n0];
                bv[kk][0] = t.x; bv[kk][1] = t.y; bv[kk][2] = t.z; bv[kk][3] = t.w;
            }
#pragma unroll
            for (int i = 0; i < 4; i++)
#pragma unroll
                for (int j = 0; j < 4; j++)
#pragma unroll
                    for (int kk = 0; kk < 4; kk++)
                        acc[i][j] = fmaf(aa[i][kk], bv[kk][j], acc[i][j]);
        }
        float4 b4 = *(const float4*)&bias_w[n0];
#pragma unroll
        for (int i = 0; i < 4; i++) {
            int mm = m0 + i;
            if (mm < cnt) {
                float* xr = g_x + (size_t)(row0 + mm) * DO + n0;
                float4 cur = *(float4*)xr;
                *(float4*)xr = make_float4(cur.x + acc[i][0] + b4.x, cur.y + acc[i][1] + b4.y,
                                           cur.z + acc[i][2] + b4.z, cur.w + acc[i][3] + b4.w);
            }
        }
    }
}

// ---------------- BN column stats ----------------
__global__ void k_stats() {
    int c = threadIdx.x;
    float s = 0.f, q = 0.f;
    for (int r = blockIdx.x; r < NE; r += gridDim.x) {
        float v = g_x[(size_t)r * DO + c];
        s += v;
        q += v * v;
    }
    atomicAdd(&g_stats[c], s);
    atomicAdd(&g_stats[DO + c], q);
}

__global__ void k_bn(const float* __restrict__ gamma, const float* __restrict__ beta) {
    int c = threadIdx.x;
    if (c < DO) {
        float mean = g_stats[c] / (float)NE;
        float var = g_stats[DO + c] / (float)NE - mean * mean;
        float sc = gamma[c] * rsqrtf(var + BN_EPS);
        g_scale[c] = sc;
        g_shift[c] = beta[c] - mean * sc;
    }
}

// ---------------- r = rel_emb @ w_rel ----------------
__global__ void k_rel(const float* __restrict__ rel_emb, const float* __restrict__ w_rel) {
    int idx = blockIdx.x * blockDim.x + threadIdx.x;
    if (idx < NR * DO) {
        int row = idx / DO, col = idx - row * DO;
        float acc = 0.f;
        for (int k = 0; k < DI; k++)
            acc = fmaf(rel_emb[row * DI + k], w_rel[k * DO + col], acc);
        g_r[idx] = acc;
    }
}

// ---------------- obj = tanh(bn(x[head])) * r[rel] -> bf16 hi/lo ----------------
__global__ void k_obj(const int* __restrict__ triples) {
    int i = blockIdx.x;
    int c = threadIdx.x;
    float v = 0.f;
    if (c < DO) {
        int h = triples[3 * i], rl = triples[3 * i + 1];
        float t = tanhf(g_x[(size_t)h * DO + c] * g_scale[c] + g_shift[c]);
        v = t * g_r[rl * DO + c];
    }
    __nv_bfloat16 hi = __float2bfloat16(v);
    g_obj_hi[i * KP + c] = hi;
    g_obj_lo[i * KP + c] = __float2bfloat16(v - __bfloat162float(hi));
}

// ---------------- emb -> bf16 hi/lo, padded to KP ----------------
__global__ void k_split_emb(const float* __restrict__ emb) {
    int row = blockIdx.x;
    int c = threadIdx.x;
    float v = (c < DO) ? emb[(size_t)row * DO + c] : 0.f;
    __nv_bfloat16 hi = __float2bfloat16(v);
    size_t idx = (size_t)row * KP + c;
    g_emb_hi[idx] = hi;
    g_emb_lo[idx] = __float2bfloat16(v - __bfloat162float(hi));
}

// ---------------- score via mma.sync ----------------
#define SSTR 144
#define PLANE (128 * SSTR)
__global__ void __launch_bounds__(256) k_score_mma(
    const float* __restrict__ ebias, float* __restrict__ out) {
    extern __shared__ char sm[];
    uint32_t sbase = smem_u32(sm);
    const uint32_t A_HI = 0, A_LO = PLANE, B_HI = 2 * PLANE, B_LO = 3 * PLANE;

    int tid = threadIdx.x, wid = tid >> 5, lane = tid & 31;
    int wm = wid >> 2, wn = wid & 3;
    int i0 = blockIdx.x * 128;
    int e0 = blockIdx.y * 128;
    int g = lane >> 2, tg = lane & 3;

    int mat = lane >> 3, r = lane & 7;
    uint32_t aoff = (uint32_t)(((mat & 1) * 8 + r) * SSTR + (mat >> 1) * 16);
    uint32_t boff = (uint32_t)(r * SSTR + ((lane >> 3) & 1) * 16);

    float acc[4][4][4] = {};

    for (int ch = 0; ch < 7; ch++) {
        int k0 = ch * 64;
        __syncthreads();
        const uint4 z4 = make_uint4(0, 0, 0, 0);
        for (int idx = tid; idx < 128 * 8; idx += 256) {
            int row = idx >> 3, seg = idx & 7;
            uint32_t so = (uint32_t)(row * SSTR + seg * 16);
            *(uint4*)(sm + A_HI + so) =
                *(const uint4*)&g_obj_hi[(size_t)(i0 + row) * KP + k0 + seg * 8];
            *(uint4*)(sm + A_LO + so) =
                *(const uint4*)&g_obj_lo[(size_t)(i0 + row) * KP + k0 + seg * 8];
            int e = e0 + row;
            uint4 vh = z4, vl = z4;
            if (e < NE) {
                vh = *(const uint4*)&g_emb_hi[(size_t)e * KP + k0 + seg * 8];
                vl = *(const uint4*)&g_emb_lo[(size_t)e * KP + k0 + seg * 8];
            }
            *(uint4*)(sm + B_HI + so) = vh;
            *(uint4*)(sm + B_LO + so) = vl;
        }
        __syncthreads();

#pragma unroll
        for (int ks = 0; ks < 4; ks++) {
            uint32_t ah[4][4], al[4][4], bh[4][2], bl[4][2];
#pragma unroll
            for (int mt = 0; mt < 4; mt++) {
                uint32_t ab = (uint32_t)((wm * 64 + mt * 16) * SSTR + ks * 32) + aoff;
                ldsm_x4(ah[mt], sbase + A_HI + ab);
                ldsm_x4(al[mt], sbase + A_LO + ab);
            }
#pragma unroll
            for (int nt = 0; nt < 4; nt++) {
                uint32_t bb = (uint32_t)((wn * 32 + nt * 8) * SSTR + ks * 32) + boff;
                ldsm_x2(bh[nt], sbase + B_HI + bb);
                ldsm_x2(bl[nt], sbase + B_LO + bb);
            }
#pragma unroll
            for (int mt = 0; mt < 4; mt++)
#pragma unroll
                for (int nt = 0; nt < 4; nt++) {
                    mma16816(acc[mt][nt], ah[mt], bh[nt]);
                    mma16816(acc[mt][nt], ah[mt], bl[nt]);
                    mma16816(acc[mt][nt], al[mt], bh[nt]);
                }
        }
    }

#pragma unroll
    for (int mt = 0; mt < 4; mt++) {
        int row = i0 + wm * 64 + mt * 16 + g;
#pragma unroll
        for (int nt = 0; nt < 4; nt++) {
            int col = e0 + wn * 32 + nt * 8 + tg * 2;
            if (col < NE) {
                float b0 = ebias[col], b1 = ebias[col + 1];
                float2 v0;
                v0.x = 1.f / (1.f + __expf(-(acc[mt][nt][0] + b0)));
                v0.y = 1.f / (1.f + __expf(-(acc[mt][nt][1] + b1)));
                *(float2*)&out[(size_t)row * NE + col] = v0;
                float2 v1;
                v1.x = 1.f / (1.f + __expf(-(acc[mt][nt][2] + b0)));
                v1.y = 1.f / (1.f + __expf(-(acc[mt][nt][3] + b1)));
                *(float2*)&out[(size_t)(row + 8) * NE + col] = v1;
            }
        }
    }
}

// ---------------- launch ----------------
extern "C" void kernel_launch(void* const* d_in, const int* in_sizes, int n_in,
                              void* d_out, int out_size) {
    const float* ent_emb  = (const float*)d_in[0];
    const float* rel_emb  = (const float*)d_in[1];
    const float* in_w     = (const float*)d_in[2];
    const float* out_w    = (const float*)d_in[3];
    const float* loop_w   = (const float*)d_in[4];
    const float* w_rel    = (const float*)d_in[5];
    const float* loop_rel = (const float*)d_in[6];
    const float* bias_w   = (const float*)d_in[7];
    const float* bn_gamma = (const float*)d_in[8];
    const float* bn_beta  = (const float*)d_in[9];
    const float* emb_ent  = (const float*)d_in[10];
    const float* ent_bias = (const float*)d_in[11];
    const int*   src      = (const int*)d_in[12];
    const int*   dst      = (const int*)d_in[13];
    const int*   et       = (const int*)d_in[14];
    const float* enorm    = (const float*)d_in[15];
    const int*   triples  = (const int*)d_in[16];
    float* out = (float*)d_out;

    const int SM_LOOP = 64 * DI * 4;
    cudaFuncSetAttribute(k_loopx, cudaFuncAttributeMaxDynamicSharedMemorySize, SM_LOOP);
    cudaFuncSetAttribute(k_edge_mma, cudaFuncAttributeMaxDynamicSharedMemorySize, EDGE_SMEM);
    const int SM_SCORE = 4 * PLANE;
    cudaFuncSetAttribute(k_score_mma, cudaFuncAttributeMaxDynamicSharedMemorySize, SM_SCORE);

    k_zero<<<4096, 256>>>();
    k_hist<<<(NEDGE + 255) / 256, 256>>>(et);
    k_scan<<<1, 1024>>>();
    k_scatter<<<(NEDGE + 255) / 256, 256>>>(et);
    k_M<<<dim3(4, 801), 256>>>(rel_emb, in_w, out_w, loop_w, loop_rel);
    k_splitM<<<dim3(98, NGROUP), 256>>>();
    k_split_emb<<<NE, KP>>>(emb_ent);
    k_edge_mma<<<dim3(12, NGROUP), 256, EDGE_SMEM>>>(ent_emb, src, dst, enorm);
    k_loopx<<<(NE + 63) / 64, 256, SM_LOOP>>>(ent_emb, bias_w);
    k_stats<<<256, 400>>>();
    k_bn<<<1, 512>>>(bn_gamma, bn_beta);
    k_rel<<<(NR * DO + 255) / 256, 256>>>(rel_emb, w_rel);
    k_obj<<<NB, KP>>>(triples);
    k_score_mma<<<dim3(NB / 128, (NE + 127) / 128), 256, SM_SCORE>>>(ent_bias, out);
}

// round 8
// speedup vs baseline: 3.3519x; 1.0639x over previous
#include <cuda_runtime.h>
#include <cuda_bf16.h>
#include <cstdint>
#include <math.h>

#define NE 100000
#define NR 400
#define DI 200
#define DO 400
#define NEDGE 600000
#define HALFE 300000
#define NB 1024
#define NGROUP 800
#define BN_EPS 1e-5f

#define KP 448      // K padded for score GEMM
#define EN 448      // padded output cols for edge GEMM
#define EK 208      // padded K for edge GEMM (13 x 16)

typedef unsigned long long u64;

// ---------------- device scratch ----------------
__device__ __nv_bfloat16 g_Mbh[(size_t)(NGROUP + 1) * EN * EK];  // bf16 hi [o_perm][t]; group 800 = loop
__device__ __nv_bfloat16 g_Mbl[(size_t)(NGROUP + 1) * EN * EK];  // bf16 lo
__device__ float g_x[(size_t)NE * DO];
__device__ float g_stats[2 * DO];
__device__ float g_scale[DO];
__device__ float g_shift[DO];
__device__ float g_r[NR * DO];
__device__ __nv_bfloat16 g_obj_hi[NB * KP];
__device__ __nv_bfloat16 g_obj_lo[NB * KP];
__device__ __nv_bfloat16 g_emb_hi[(size_t)NE * KP];
__device__ __nv_bfloat16 g_emb_lo[(size_t)NE * KP];
__device__ int   g_hist[NGROUP];
__device__ int   g_off[NGROUP + 1];
__device__ int   g_pos[NGROUP];
__device__ int   g_eidx[NEDGE];

// ---------------- helpers ----------------
__device__ __forceinline__ void red4(float* p, float a, float b, float c, float d) {
    asm volatile("red.global.add.v4.f32 [%0], {%1,%2,%3,%4};"
                 :: "l"(p), "f"(a), "f"(b), "f"(c), "f"(d) : "memory");
}
__device__ __forceinline__ uint32_t smem_u32(const void* p) {
    uint32_t a;
    asm("{ .reg .u64 t; cvta.to.shared.u64 t, %1; cvt.u32.u64 %0, t; }" : "=r"(a) : "l"(p));
    return a;
}
__device__ __forceinline__ void ldsm_x4(uint32_t* r, uint32_t a) {
    asm volatile("ldmatrix.sync.aligned.m8n8.x4.shared.b16 {%0,%1,%2,%3}, [%4];"
                 : "=r"(r[0]), "=r"(r[1]), "=r"(r[2]), "=r"(r[3]) : "r"(a));
}
__device__ __forceinline__ void ldsm_x2(uint32_t* r, uint32_t a) {
    asm volatile("ldmatrix.sync.aligned.m8n8.x2.shared.b16 {%0,%1}, [%2];"
                 : "=r"(r[0]), "=r"(r[1]) : "r"(a));
}
__device__ __forceinline__ void mma16816(float* d, const uint32_t* a, const uint32_t* b) {
    asm volatile(
        "mma.sync.aligned.m16n8k16.row.col.f32.bf16.bf16.f32 "
        "{%0,%1,%2,%3}, {%4,%5,%6,%7}, {%8,%9}, {%0,%1,%2,%3};"
        : "+f"(d[0]), "+f"(d[1]), "+f"(d[2]), "+f"(d[3])
        : "r"(a[0]), "r"(a[1]), "r"(a[2]), "r"(a[3]), "r"(b[0]), "r"(b[1]));
}
__device__ __forceinline__ ushort bf16h(float v) {
    return __bfloat16_as_ushort(__float2bfloat16(v));
}
__device__ __forceinline__ ushort bf16l(float v) {
    __nv_bfloat16 h = __float2bfloat16(v);
    return __bfloat16_as_ushort(__float2bfloat16(v - __bfloat162float(h)));
}

// ---------------- zero scratch ----------------
__global__ void k_zero() {
    const size_t n4 = (size_t)NE * DO / 4;
    float4* p = reinterpret_cast<float4*>(g_x);
    const float4 z = make_float4(0.f, 0.f, 0.f, 0.f);
    for (size_t i = (size_t)blockIdx.x * blockDim.x + threadIdx.x; i < n4;
         i += (size_t)gridDim.x * blockDim.x)
        p[i] = z;
    int gid = blockIdx.x * blockDim.x + threadIdx.x;
    if (gid < NGROUP) g_hist[gid] = 0;
    if (gid < 2 * DO) g_stats[gid] = 0.f;
}

// ---------------- edge grouping ----------------
__global__ void k_hist(const int* __restrict__ et) {
    int e = blockIdx.x * blockDim.x + threadIdx.x;
    if (e < NEDGE) atomicAdd(&g_hist[et[e] + (e < HALFE ? 0 : 400)], 1);
}

__global__ void k_scan() {
    __shared__ int s[NGROUP];
    int i = threadIdx.x;
    if (i < NGROUP) s[i] = g_hist[i];
    __syncthreads();
    for (int d = 1; d < NGROUP; d <<= 1) {
        int v = 0;
        if (i < NGROUP && i >= d) v = s[i - d];
        __syncthreads();
        if (i < NGROUP && i >= d) s[i] += v;
        __syncthreads();
    }
    if (i < NGROUP) {
        int excl = s[i] - g_hist[i];
        g_off[i] = excl;
        g_pos[i] = excl;
        if (i == NGROUP - 1) g_off[NGROUP] = s[i];
    }
}

__global__ void k_scatter(const int* __restrict__ et) {
    int e = blockIdx.x * blockDim.x + threadIdx.x;
    if (e < NEDGE) {
        int p = atomicAdd(&g_pos[et[e] + (e < HALFE ? 0 : 400)], 1);
        g_eidx[p] = e;
    }
}

// ---------------- M precompute with fused transpose + bf16 split ----------------
// M[t,o] = (1/3) sum_j b[(t+j)%200] W[j,o]; writes hi/lo planes [o_perm][t]
__global__ void __launch_bounds__(256) k_M(
    const float* __restrict__ rel_emb, const float* __restrict__ in_w,
    const float* __restrict__ out_w, const float* __restrict__ loop_w,
    const float* __restrict__ loop_rel) {
    __shared__ float bb[464];
    int m = blockIdx.y;
    const float* bsrc;
    const float* W;
    if (m < 800) {
        int h = m / 400, r = m - h * 400;
        bsrc = rel_emb + (size_t)r * DI;
        W = h ? out_w : in_w;
    } else {
        bsrc = loop_rel;
        W = loop_w;
    }
    int tid = threadIdx.x;
    for (int s = tid; s < 464; s += 256) bb[s] = bsrc[s % DI];
    __syncthreads();

    int te = tid >> 4, to = tid & 15;
    int t0 = blockIdx.x * 64 + te * 4;
    const float S = 1.f / 3.f;

    for (int ot = 0; ot < 7; ++ot) {
        int n0 = ot * 64 + to * 4;
        if (n0 >= DO) continue;
        float acc[4][4] = {};
        for (int k = 0; k < DI; k += 4) {
            float aa[4][4], bv[4][4];
#pragma unroll
            for (int i = 0; i < 4; i++)
#pragma unroll
                for (int kk = 0; kk < 4; kk++)
                    aa[i][kk] = bb[t0 + i + k + kk];
#pragma unroll
            for (int kk = 0; kk < 4; kk++) {
                float4 t = *(const float4*)&W[(size_t)(k + kk) * DO + n0];
                bv[kk][0] = t.x; bv[kk][1] = t.y; bv[kk][2] = t.z; bv[kk][3] = t.w;
            }
#pragma unroll
            for (int i = 0; i < 4; i++)
#pragma unroll
                for (int j = 0; j < 4; j++)
#pragma unroll
                    for (int kk = 0; kk < 4; kk++)
                        acc[i][j] = fmaf(aa[i][kk], bv[kk][j], acc[i][j]);
        }
        if (t0 < EK) {
#pragma unroll
            for (int j = 0; j < 4; j++) {
                int o = n0 + j;
                int ml = o & 15;
                int pm = ((ml & 2) << 2) | ((ml & 12) >> 1) | (ml & 1);
                int op = (o & ~15) | pm;
                float v0 = acc[0][j] * S, v1 = acc[1][j] * S;
                float v2 = acc[2][j] * S, v3 = acc[3][j] * S;
                ushort4 h4, l4;
                h4.x = bf16h(v0); h4.y = bf16h(v1); h4.z = bf16h(v2); h4.w = bf16h(v3);
                l4.x = bf16l(v0); l4.y = bf16l(v1); l4.z = bf16l(v2); l4.w = bf16l(v3);
                size_t off = ((size_t)m * EN + op) * EK + t0;
                *(ushort4*)&g_Mbh[off] = h4;
                *(ushort4*)&g_Mbl[off] = l4;
            }
        }
    }
}

// ---------------- edge messages via mma.sync + red4 scatter ----------------
#define ASTR 432
#define BSTR 48
#define A_BYTES (64 * ASTR)
#define B_BYTES (EN * BSTR)
#define EDGE_SMEM (2 * A_BYTES + 2 * B_BYTES)

__global__ void __launch_bounds__(256) k_edge_mma(
    const float* __restrict__ ent_emb, const int* __restrict__ src,
    const int* __restrict__ dst, const float* __restrict__ nrm) {
    extern __shared__ char sm[];
    uint32_t sbase = smem_u32(sm);
    const uint32_t A_HI = 0, A_LO = A_BYTES, B_HI = 2 * A_BYTES, B_LO = 2 * A_BYTES + B_BYTES;
    __shared__ int s_src[64];
    __shared__ int s_dst[64];
    __shared__ float s_nrm[64];

    int g = blockIdx.y;
    int base = g_off[g];
    int ng = g_off[g + 1] - base;
    int tid = threadIdx.x, wid = tid >> 5, lane = tid & 31;
    int wm = wid >> 2, wn = wid & 3;
    int gq = lane >> 2, tg = lane & 3;
    int mat = lane >> 3, r = lane & 7;
    uint32_t aoff = (uint32_t)(((mat & 1) * 8 + r) * ASTR + (mat >> 1) * 16);
    uint32_t boff = (uint32_t)(r * BSTR + ((lane >> 3) & 1) * 16);
    const __nv_bfloat16* Bh = g_Mbh + (size_t)g * EN * EK;
    const __nv_bfloat16* Bl = g_Mbl + (size_t)g * EN * EK;

    for (int t0 = blockIdx.x * 64; t0 < ng; t0 += gridDim.x * 64) {
        int cnt = min(64, ng - t0);
        __syncthreads();
        if (tid < 64) {
            if (tid < cnt) {
                int e = g_eidx[base + t0 + tid];
                s_src[tid] = src[e];
                s_dst[tid] = dst[e];
                s_nrm[tid] = nrm[e];
            } else {
                s_src[tid] = 0;
                s_dst[tid] = 0;
                s_nrm[tid] = 0.f;
            }
        }
        __syncthreads();
        for (int idx = tid; idx < 64 * 26; idx += 256) {
            int row = idx / 26, seg = idx - row * 26;
            uint32_t hi4[4] = {0, 0, 0, 0}, lo4[4] = {0, 0, 0, 0};
            if (seg < 25) {
                const float* p = &ent_emb[(size_t)s_src[row] * DI + seg * 8];
                float nv = s_nrm[row];
#pragma unroll
                for (int q = 0; q < 4; q++) {
                    float v0 = p[q * 2] * nv, v1 = p[q * 2 + 1] * nv;
                    hi4[q] = (uint32_t)bf16h(v0) | ((uint32_t)bf16h(v1) << 16);
                    lo4[q] = (uint32_t)bf16l(v0) | ((uint32_t)bf16l(v1) << 16);
                }
            }
            uint32_t so = (uint32_t)(row * ASTR + seg * 16);
            *(uint4*)(sm + A_HI + so) = make_uint4(hi4[0], hi4[1], hi4[2], hi4[3]);
            *(uint4*)(sm + A_LO + so) = make_uint4(lo4[0], lo4[1], lo4[2], lo4[3]);
        }

        float acc[2][14][4];
#pragma unroll
        for (int mt = 0; mt < 2; mt++)
#pragma unroll
            for (int nt = 0; nt < 14; nt++)
#pragma unroll
                for (int q = 0; q < 4; q++) acc[mt][nt][q] = 0.f;

        for (int kc = 0; kc < 13; kc++) {
            __syncthreads();
            for (int idx = tid; idx < EN * 2; idx += 256) {
                int o = idx >> 1, half = idx & 1;
                size_t goff = (size_t)o * EK + kc * 16 + half * 8;
                *(uint4*)(sm + B_HI + o * BSTR + half * 16) = *(const uint4*)&Bh[goff];
                *(uint4*)(sm + B_LO + o * BSTR + half * 16) = *(const uint4*)&Bl[goff];
            }
            __syncthreads();
            uint32_t ah[2][4], al[2][4];
#pragma unroll
            for (int mt = 0; mt < 2; mt++) {
                uint32_t ab = (uint32_t)((wm * 32 + mt * 16) * ASTR + kc * 32) + aoff;
                ldsm_x4(ah[mt], sbase + A_HI + ab);
                ldsm_x4(al[mt], sbase + A_LO + ab);
            }
#pragma unroll
            for (int nt = 0; nt < 14; nt++) {
                uint32_t bh[2], bl[2];
                uint32_t bb = (uint32_t)((wn * 112 + nt * 8) * BSTR) + boff;
                ldsm_x2(bh, sbase + B_HI + bb);
                ldsm_x2(bl, sbase + B_LO + bb);
#pragma unroll
                for (int mt = 0; mt < 2; mt++) {
                    mma16816(acc[mt][nt], ah[mt], bh);
                    mma16816(acc[mt][nt], ah[mt], bl);
                    mma16816(acc[mt][nt], al[mt], bh);
                }
            }
        }

#pragma unroll
        for (int mt = 0; mt < 2; mt++) {
            int er0 = wm * 32 + mt * 16 + gq;
            int er1 = er0 + 8;
#pragma unroll
            for (int qt = 0; qt < 7; qt++) {
                int c = wn * 112 + qt * 16 + tg * 4;
                if (c < DO) {
                    float* a0 = acc[mt][2 * qt];
                    float* a1 = acc[mt][2 * qt + 1];
                    if (er0 < cnt)
                        red4(&g_x[(size_t)s_dst[er0] * DO + c], a0[0], a0[1], a1[0], a1[1]);
                    if (er1 < cnt)
                        red4(&g_x[(size_t)s_dst[er1] * DO + c], a0[2], a0[3], a1[2], a1[3]);
                }
            }
        }
    }
}

// ---------------- self-loop via mma.sync: x = agg + loop + bias ----------------
__global__ void __launch_bounds__(256) k_loopx_mma(
    const float* __restrict__ ent_emb, const float* __restrict__ bias_w) {
    extern __shared__ char sm[];
    uint32_t sbase = smem_u32(sm);
    const uint32_t A_HI = 0, A_LO = A_BYTES, B_HI = 2 * A_BYTES, B_LO = 2 * A_BYTES + B_BYTES;

    int tid = threadIdx.x, wid = tid >> 5, lane = tid & 31;
    int wm = wid >> 2, wn = wid & 3;
    int gq = lane >> 2, tg = lane & 3;
    int mat = lane >> 3, r = lane & 7;
    uint32_t aoff = (uint32_t)(((mat & 1) * 8 + r) * ASTR + (mat >> 1) * 16);
    uint32_t boff = (uint32_t)(r * BSTR + ((lane >> 3) & 1) * 16);
    const __nv_bfloat16* Bh = g_Mbh + (size_t)NGROUP * EN * EK;
    const __nv_bfloat16* Bl = g_Mbl + (size_t)NGROUP * EN * EK;

    int row0 = blockIdx.x * 64;
    int cnt = min(64, NE - row0);

    for (int idx = tid; idx < 64 * 26; idx += 256) {
        int row = idx / 26, seg = idx - row * 26;
        uint32_t hi4[4] = {0, 0, 0, 0}, lo4[4] = {0, 0, 0, 0};
        if (seg < 25 && row < cnt) {
            const float* p = &ent_emb[(size_t)(row0 + row) * DI + seg * 8];
#pragma unroll
            for (int q = 0; q < 4; q++) {
                float v0 = p[q * 2], v1 = p[q * 2 + 1];
                hi4[q] = (uint32_t)bf16h(v0) | ((uint32_t)bf16h(v1) << 16);
                lo4[q] = (uint32_t)bf16l(v0) | ((uint32_t)bf16l(v1) << 16);
            }
        }
        uint32_t so = (uint32_t)(row * ASTR + seg * 16);
        *(uint4*)(sm + A_HI + so) = make_uint4(hi4[0], hi4[1], hi4[2], hi4[3]);
        *(uint4*)(sm + A_LO + so) = make_uint4(lo4[0], lo4[1], lo4[2], lo4[3]);
    }

    float acc[2][14][4];
#pragma unroll
    for (int mt = 0; mt < 2; mt++)
#pragma unroll
        for (int nt = 0; nt < 14; nt++)
#pragma unroll
            for (int q = 0; q < 4; q++) acc[mt][nt][q] = 0.f;

    for (int kc = 0; kc < 13; kc++) {
        __syncthreads();
        for (int idx = tid; idx < EN * 2; idx += 256) {
            int o = idx >> 1, half = idx & 1;
            size_t goff = (size_t)o * EK + kc * 16 + half * 8;
            *(uint4*)(sm + B_HI + o * BSTR + half * 16) = *(const uint4*)&Bh[goff];
            *(uint4*)(sm + B_LO + o * BSTR + half * 16) = *(const uint4*)&Bl[goff];
        }
        __syncthreads();
        uint32_t ah[2][4], al[2][4];
#pragma unroll
        for (int mt = 0; mt < 2; mt++) {
            uint32_t ab = (uint32_t)((wm * 32 + mt * 16) * ASTR + kc * 32) + aoff;
            ldsm_x4(ah[mt], sbase + A_HI + ab);
            ldsm_x4(al[mt], sbase + A_LO + ab);
        }
#pragma unroll
        for (int nt = 0; nt < 14; nt++) {
            uint32_t bh[2], bl[2];
            uint32_t bb = (uint32_t)((wn * 112 + nt * 8) * BSTR) + boff;
            ldsm_x2(bh, sbase + B_HI + bb);
            ldsm_x2(bl, sbase + B_LO + bb);
#pragma unroll
            for (int mt = 0; mt < 2; mt++) {
                mma16816(acc[mt][nt], ah[mt], bh);
                mma16816(acc[mt][nt], ah[mt], bl);
                mma16816(acc[mt][nt], al[mt], bh);
            }
        }
    }

#pragma unroll
    for (int mt = 0; mt < 2; mt++) {
        int er0 = wm * 32 + mt * 16 + gq;
        int er1 = er0 + 8;
#pragma unroll
        for (int qt = 0; qt < 7; qt++) {
            int c = wn * 112 + qt * 16 + tg * 4;
            if (c < DO) {
                float4 b4 = *(const float4*)&bias_w[c];
                float* a0 = acc[mt][2 * qt];
                float* a1 = acc[mt][2 * qt + 1];
                if (er0 < cnt) {
                    float* xr = &g_x[(size_t)(row0 + er0) * DO + c];
                    float4 cur = *(float4*)xr;
                    *(float4*)xr = make_float4(cur.x + a0[0] + b4.x, cur.y + a0[1] + b4.y,
                                               cur.z + a1[0] + b4.z, cur.w + a1[1] + b4.w);
                }
                if (er1 < cnt) {
                    float* xr = &g_x[(size_t)(row0 + er1) * DO + c];
                    float4 cur = *(float4*)xr;
                    *(float4*)xr = make_float4(cur.x + a0[2] + b4.x, cur.y + a0[3] + b4.y,
                                               cur.z + a1[2] + b4.z, cur.w + a1[3] + b4.w);
                }
            }
        }
    }
}

// ---------------- BN column stats ----------------
__global__ void k_stats() {
    int c = threadIdx.x;
    float s = 0.f, q = 0.f;
    for (int r = blockIdx.x; r < NE; r += gridDim.x) {
        float v = g_x[(size_t)r * DO + c];
        s += v;
        q += v * v;
    }
    atomicAdd(&g_stats[c], s);
    atomicAdd(&g_stats[DO + c], q);
}

__global__ void k_bn(const float* __restrict__ gamma, const float* __restrict__ beta) {
    int c = threadIdx.x;
    if (c < DO) {
        float mean = g_stats[c] / (float)NE;
        float var = g_stats[DO + c] / (float)NE - mean * mean;
        float sc = gamma[c] * rsqrtf(var + BN_EPS);
        g_scale[c] = sc;
        g_shift[c] = beta[c] - mean * sc;
    }
}

// ---------------- r = rel_emb @ w_rel ----------------
__global__ void k_rel(const float* __restrict__ rel_emb, const float* __restrict__ w_rel) {
    int idx = blockIdx.x * blockDim.x + threadIdx.x;
    if (idx < NR * DO) {
        int row = idx / DO, col = idx - row * DO;
        float acc = 0.f;
        for (int k = 0; k < DI; k++)
            acc = fmaf(rel_emb[row * DI + k], w_rel[k * DO + col], acc);
        g_r[idx] = acc;
    }
}

// ---------------- obj = tanh(bn(x[head])) * r[rel] -> bf16 hi/lo ----------------
__global__ void k_obj(const int* __restrict__ triples) {
    int i = blockIdx.x;
    int c = threadIdx.x;
    float v = 0.f;
    if (c < DO) {
        int h = triples[3 * i], rl = triples[3 * i + 1];
        float t = tanhf(g_x[(size_t)h * DO + c] * g_scale[c] + g_shift[c]);
        v = t * g_r[rl * DO + c];
    }
    __nv_bfloat16 hi = __float2bfloat16(v);
    g_obj_hi[i * KP + c] = hi;
    g_obj_lo[i * KP + c] = __float2bfloat16(v - __bfloat162float(hi));
}

// ---------------- emb -> bf16 hi/lo, padded to KP ----------------
__global__ void k_split_emb(const float* __restrict__ emb) {
    int row = blockIdx.x;
    int c = threadIdx.x;
    float v = (c < DO) ? emb[(size_t)row * DO + c] : 0.f;
    __nv_bfloat16 hi = __float2bfloat16(v);
    size_t idx = (size_t)row * KP + c;
    g_emb_hi[idx] = hi;
    g_emb_lo[idx] = __float2bfloat16(v - __bfloat162float(hi));
}

// ---------------- score via mma.sync ----------------
#define SSTR 144
#define PLANE (128 * SSTR)
__global__ void __launch_bounds__(256) k_score_mma(
    const float* __restrict__ ebias, float* __restrict__ out) {
    extern __shared__ char sm[];
    uint32_t sbase = smem_u32(sm);
    const uint32_t A_HI = 0, A_LO = PLANE, B_HI = 2 * PLANE, B_LO = 3 * PLANE;

    int tid = threadIdx.x, wid = tid >> 5, lane = tid & 31;
    int wm = wid >> 2, wn = wid & 3;
    int i0 = blockIdx.x * 128;
    int e0 = blockIdx.y * 128;
    int g = lane >> 2, tg = lane & 3;

    int mat = lane >> 3, r = lane & 7;
    uint32_t aoff = (uint32_t)(((mat & 1) * 8 + r) * SSTR + (mat >> 1) * 16);
    uint32_t boff = (uint32_t)(r * SSTR + ((lane >> 3) & 1) * 16);

    float acc[4][4][4] = {};

    for (int ch = 0; ch < 7; ch++) {
        int k0 = ch * 64;
        __syncthreads();
        const uint4 z4 = make_uint4(0, 0, 0, 0);
        for (int idx = tid; idx < 128 * 8; idx += 256) {
            int row = idx >> 3, seg = idx & 7;
            uint32_t so = (uint32_t)(row * SSTR + seg * 16);
            *(uint4*)(sm + A_HI + so) =
                *(const uint4*)&g_obj_hi[(size_t)(i0 + row) * KP + k0 + seg * 8];
            *(uint4*)(sm + A_LO + so) =
                *(const uint4*)&g_obj_lo[(size_t)(i0 + row) * KP + k0 + seg * 8];
            int e = e0 + row;
            uint4 vh = z4, vl = z4;
            if (e < NE) {
                vh = *(const uint4*)&g_emb_hi[(size_t)e * KP + k0 + seg * 8];
                vl = *(const uint4*)&g_emb_lo[(size_t)e * KP + k0 + seg * 8];
            }
            *(uint4*)(sm + B_HI + so) = vh;
            *(uint4*)(sm + B_LO + so) = vl;
        }
        __syncthreads();

#pragma unroll
        for (int ks = 0; ks < 4; ks++) {
            uint32_t ah[4][4], al[4][4], bh[4][2], bl[4][2];
#pragma unroll
            for (int mt = 0; mt < 4; mt++) {
                uint32_t ab = (uint32_t)((wm * 64 + mt * 16) * SSTR + ks * 32) + aoff;
                ldsm_x4(ah[mt], sbase + A_HI + ab);
                ldsm_x4(al[mt], sbase + A_LO + ab);
            }
#pragma unroll
            for (int nt = 0; nt < 4; nt++) {
                uint32_t bb = (uint32_t)((wn * 32 + nt * 8) * SSTR + ks * 32) + boff;
                ldsm_x2(bh[nt], sbase + B_HI + bb);
                ldsm_x2(bl[nt], sbase + B_LO + bb);
            }
#pragma unroll
            for (int mt = 0; mt < 4; mt++)
#pragma unroll
                for (int nt = 0; nt < 4; nt++) {
                    mma16816(acc[mt][nt], ah[mt], bh[nt]);
                    mma16816(acc[mt][nt], ah[mt], bl[nt]);
                    mma16816(acc[mt][nt], al[mt], bh[nt]);
                }
        }
    }

#pragma unroll
    for (int mt = 0; mt < 4; mt++) {
        int row = i0 + wm * 64 + mt * 16 + g;
#pragma unroll
        for (int nt = 0; nt < 4; nt++) {
            int col = e0 + wn * 32 + nt * 8 + tg * 2;
            if (col < NE) {
                float b0 = ebias[col], b1 = ebias[col + 1];
                float2 v0;
                v0.x = 1.f / (1.f + __expf(-(acc[mt][nt][0] + b0)));
                v0.y = 1.f / (1.f + __expf(-(acc[mt][nt][1] + b1)));
                *(float2*)&out[(size_t)row * NE + col] = v0;
                float2 v1;
                v1.x = 1.f / (1.f + __expf(-(acc[mt][nt][2] + b0)));
                v1.y = 1.f / (1.f + __expf(-(acc[mt][nt][3] + b1)));
                *(float2*)&out[(size_t)(row + 8) * NE + col] = v1;
            }
        }
    }
}

// ---------------- launch ----------------
extern "C" void kernel_launch(void* const* d_in, const int* in_sizes, int n_in,
                              void* d_out, int out_size) {
    const float* ent_emb  = (const float*)d_in[0];
    const float* rel_emb  = (const float*)d_in[1];
    const float* in_w     = (const float*)d_in[2];
    const float* out_w    = (const float*)d_in[3];
    const float* loop_w   = (const float*)d_in[4];
    const float* w_rel    = (const float*)d_in[5];
    const float* loop_rel = (const float*)d_in[6];
    const float* bias_w   = (const float*)d_in[7];
    const float* bn_gamma = (const float*)d_in[8];
    const float* bn_beta  = (const float*)d_in[9];
    const float* emb_ent  = (const float*)d_in[10];
    const float* ent_bias = (const float*)d_in[11];
    const int*   src      = (const int*)d_in[12];
    const int*   dst      = (const int*)d_in[13];
    const int*   et       = (const int*)d_in[14];
    const float* enorm    = (const float*)d_in[15];
    const int*   triples  = (const int*)d_in[16];
    float* out = (float*)d_out;

    cudaFuncSetAttribute(k_edge_mma, cudaFuncAttributeMaxDynamicSharedMemorySize, EDGE_SMEM);
    cudaFuncSetAttribute(k_loopx_mma, cudaFuncAttributeMaxDynamicSharedMemorySize, EDGE_SMEM);
    const int SM_SCORE = 4 * PLANE;
    cudaFuncSetAttribute(k_score_mma, cudaFuncAttributeMaxDynamicSharedMemorySize, SM_SCORE);

    k_zero<<<4096, 256>>>();
    k_hist<<<(NEDGE + 255) / 256, 256>>>(et);
    k_scan<<<1, 1024>>>();
    k_scatter<<<(NEDGE + 255) / 256, 256>>>(et);
    k_M<<<dim3(4, 801), 256>>>(rel_emb, in_w, out_w, loop_w, loop_rel);
    k_split_emb<<<NE, KP>>>(emb_ent);
    k_edge_mma<<<dim3(12, NGROUP), 256, EDGE_SMEM>>>(ent_emb, src, dst, enorm);
    k_loopx_mma<<<(NE + 63) / 64, 256, EDGE_SMEM>>>(ent_emb, bias_w);
    k_stats<<<256, 400>>>();
    k_bn<<<1, 512>>>(bn_gamma, bn_beta);
    k_rel<<<(NR * DO + 255) / 256, 256>>>(rel_emb, w_rel);
    k_obj<<<NB, KP>>>(triples);
    k_score_mma<<<dim3(NB / 128, (NE + 127) / 128), 256, SM_SCORE>>>(ent_bias, out);
}

// round 9
// speedup vs baseline: 4.1766x; 1.2460x over previous
#include <cuda_runtime.h>
#include <cuda_bf16.h>
#include <cstdint>
#include <math.h>

#define NE 100000
#define NR 400
#define DI 200
#define DO 400
#define NEDGE 600000
#define HALFE 300000
#define NB 1024
#define NGROUP 800
#define BN_EPS 1e-5f

#define KP 448      // K padded for score GEMM
#define EN 448      // padded output cols
#define EK 208      // padded K (13 x 16)

typedef unsigned long long u64;

// ---------------- device scratch ----------------
__device__ __nv_bfloat16 g_Mbh[(size_t)(NGROUP + 1) * EN * EK];  // hi [o_perm][t]; group 800 = loop
__device__ __nv_bfloat16 g_Mbl[(size_t)(NGROUP + 1) * EN * EK];  // lo
__device__ __nv_bfloat16 g_Wth[(size_t)3 * 448 * EK];            // W^T hi (in, out, loop)
__device__ __nv_bfloat16 g_Wtl[(size_t)3 * 448 * EK];            // W^T lo
__device__ float g_x[(size_t)NE * DO];
__device__ float g_stats[2 * DO];
__device__ float g_scale[DO];
__device__ float g_shift[DO];
__device__ float g_r[NR * DO];
__device__ __nv_bfloat16 g_obj_hi[NB * KP];
__device__ __nv_bfloat16 g_obj_lo[NB * KP];
__device__ __nv_bfloat16 g_emb_hi[(size_t)NE * KP];
__device__ __nv_bfloat16 g_emb_lo[(size_t)NE * KP];
__device__ int   g_hist[NGROUP];
__device__ int   g_off[NGROUP + 1];
__device__ int   g_pos[NGROUP];
__device__ int   g_eidx[NEDGE];

// ---------------- helpers ----------------
__device__ __forceinline__ void red4(float* p, float a, float b, float c, float d) {
    asm volatile("red.global.add.v4.f32 [%0], {%1,%2,%3,%4};"
                 :: "l"(p), "f"(a), "f"(b), "f"(c), "f"(d) : "memory");
}
__device__ __forceinline__ uint32_t smem_u32(const void* p) {
    uint32_t a;
    asm("{ .reg .u64 t; cvta.to.shared.u64 t, %1; cvt.u32.u64 %0, t; }" : "=r"(a) : "l"(p));
    return a;
}
__device__ __forceinline__ void ldsm_x4(uint32_t* r, uint32_t a) {
    asm volatile("ldmatrix.sync.aligned.m8n8.x4.shared.b16 {%0,%1,%2,%3}, [%4];"
                 : "=r"(r[0]), "=r"(r[1]), "=r"(r[2]), "=r"(r[3]) : "r"(a));
}
__device__ __forceinline__ void ldsm_x2(uint32_t* r, uint32_t a) {
    asm volatile("ldmatrix.sync.aligned.m8n8.x2.shared.b16 {%0,%1}, [%2];"
                 : "=r"(r[0]), "=r"(r[1]) : "r"(a));
}
__device__ __forceinline__ void mma16816(float* d, const uint32_t* a, const uint32_t* b) {
    asm volatile(
        "mma.sync.aligned.m16n8k16.row.col.f32.bf16.bf16.f32 "
        "{%0,%1,%2,%3}, {%4,%5,%6,%7}, {%8,%9}, {%0,%1,%2,%3};"
        : "+f"(d[0]), "+f"(d[1]), "+f"(d[2]), "+f"(d[3])
        : "r"(a[0]), "r"(a[1]), "r"(a[2]), "r"(a[3]), "r"(b[0]), "r"(b[1]));
}
__device__ __forceinline__ ushort bf16h(float v) {
    return __bfloat16_as_ushort(__float2bfloat16(v));
}
__device__ __forceinline__ ushort bf16l(float v) {
    __nv_bfloat16 h = __float2bfloat16(v);
    return __bfloat16_as_ushort(__float2bfloat16(v - __bfloat162float(h)));
}

// ---------------- zero scratch ----------------
__global__ void k_zero() {
    const size_t n4 = (size_t)NE * DO / 4;
    float4* p = reinterpret_cast<float4*>(g_x);
    const float4 z = make_float4(0.f, 0.f, 0.f, 0.f);
    for (size_t i = (size_t)blockIdx.x * blockDim.x + threadIdx.x; i < n4;
         i += (size_t)gridDim.x * blockDim.x)
        p[i] = z;
    int gid = blockIdx.x * blockDim.x + threadIdx.x;
    if (gid < NGROUP) g_hist[gid] = 0;
    if (gid < 2 * DO) g_stats[gid] = 0.f;
}

// ---------------- edge grouping ----------------
__global__ void k_hist(const int* __restrict__ et) {
    int e = blockIdx.x * blockDim.x + threadIdx.x;
    if (e < NEDGE) atomicAdd(&g_hist[et[e] + (e < HALFE ? 0 : 400)], 1);
}

__global__ void k_scan() {
    __shared__ int s[NGROUP];
    int i = threadIdx.x;
    if (i < NGROUP) s[i] = g_hist[i];
    __syncthreads();
    for (int d = 1; d < NGROUP; d <<= 1) {
        int v = 0;
        if (i < NGROUP && i >= d) v = s[i - d];
        __syncthreads();
        if (i < NGROUP && i >= d) s[i] += v;
        __syncthreads();
    }
    if (i < NGROUP) {
        int excl = s[i] - g_hist[i];
        g_off[i] = excl;
        g_pos[i] = excl;
        if (i == NGROUP - 1) g_off[NGROUP] = s[i];
    }
}

__global__ void k_scatter(const int* __restrict__ et) {
    int e = blockIdx.x * blockDim.x + threadIdx.x;
    if (e < NEDGE) {
        int p = atomicAdd(&g_pos[et[e] + (e < HALFE ? 0 : 400)], 1);
        g_eidx[p] = e;
    }
}

// ---------------- W^T bf16 split (once) ----------------
__global__ void k_splitW(const float* __restrict__ in_w, const float* __restrict__ out_w,
                         const float* __restrict__ loop_w) {
    int widx = blockIdx.y, o = blockIdx.x;
    const float* W = widx == 0 ? in_w : (widx == 1 ? out_w : loop_w);
    for (int j = threadIdx.x; j < EK; j += 256) {
        float v = (j < DI && o < DO) ? W[(size_t)j * DO + o] : 0.f;
        size_t off = ((size_t)widx * 448 + o) * EK + j;
        g_Wth[off] = __float2bfloat16(v);
        __nv_bfloat16 h = __float2bfloat16(v);
        g_Wtl[off] = __float2bfloat16(v - __bfloat162float(h));
    }
}

// ---------------- M^T = W^T @ C_b^T via mma.sync, fused bf16 split + perm ----------------
#define MB 48
__global__ void __launch_bounds__(256) k_M_mma(
    const float* __restrict__ rel_emb, const float* __restrict__ loop_rel) {
    __shared__ ushort s_b[4][472];   // [hi, hi_shift1, lo, lo_shift1]
    __shared__ char sA[2][64 * MB];
    __shared__ char sB[2][208 * MB];

    int m = blockIdx.y, strip = blockIdx.x;
    int widx = m < 400 ? 0 : (m < 800 ? 1 : 2);
    const float* bsrc = (m < 800) ? rel_emb + (size_t)(m % 400) * DI : loop_rel;
    int tid = threadIdx.x;

    for (int s = tid; s < 464; s += 256) {
        float v0 = bsrc[s % DI];
        float v1 = bsrc[(s + 1) % DI];
        s_b[0][s] = bf16h(v0);
        s_b[2][s] = bf16l(v0);
        s_b[1][s] = bf16h(v1);
        s_b[3][s] = bf16l(v1);
    }

    int wid = tid >> 5, lane = tid & 31;
    int wm = wid >> 1, wn = wid & 1;
    int gq = lane >> 2, tg = lane & 3;
    int mat = lane >> 3, r = lane & 7;
    uint32_t aoff = (uint32_t)(((mat & 1) * 8 + r) * MB + (mat >> 1) * 16);
    uint32_t boff = (uint32_t)(r * MB + ((lane >> 3) & 1) * 16);
    uint32_t baseA0 = smem_u32(sA[0]), baseA1 = smem_u32(sA[1]);
    uint32_t baseB0 = smem_u32(sB[0]), baseB1 = smem_u32(sB[1]);

    float acc[13][4] = {};

    for (int kc = 0; kc < 13; kc++) {
        __syncthreads();
        // stage A chunk (64 rows x 32B x 2 planes) — exactly 256 uint4 tasks
        {
            int idx = tid;
            int p = idx >> 7, rem = idx & 127;
            int row = rem >> 1, half = rem & 1;
            const __nv_bfloat16* gW = p ? g_Wtl : g_Wth;
            size_t goff = ((size_t)widx * 448 + strip * 64 + row) * EK + kc * 16 + half * 8;
            *(uint4*)(sA[p] + row * MB + half * 16) = *(const uint4*)&gW[goff];
        }
        // build circulant B chunk (208 rows x 32B x 2 planes)
        for (int idx = tid; idx < 416; idx += 256) {
            int p = (idx >= 208) ? 1 : 0;
            int t = idx - p * 208;
            int bi = t + kc * 16;
            int par = bi & 1;
            const uint32_t* sp = (const uint32_t*)&s_b[p * 2 + par][bi - par];
            uint32_t w0 = sp[0], w1 = sp[1], w2 = sp[2], w3 = sp[3];
            uint32_t w4 = sp[4], w5 = sp[5], w6 = sp[6], w7 = sp[7];
            *(uint4*)(sB[p] + t * MB) = make_uint4(w0, w1, w2, w3);
            *(uint4*)(sB[p] + t * MB + 16) = make_uint4(w4, w5, w6, w7);
        }
        __syncthreads();
        uint32_t ah[4], al[4];
        uint32_t ab = (uint32_t)((wm * 16) * MB) + aoff;
        ldsm_x4(ah, baseA0 + ab);
        ldsm_x4(al, baseA1 + ab);
#pragma unroll
        for (int nt = 0; nt < 13; nt++) {
            uint32_t bh2[2], bl2[2];
            uint32_t bb = (uint32_t)((wn * 104 + nt * 8) * MB) + boff;
            ldsm_x2(bh2, baseB0 + bb);
            ldsm_x2(bl2, baseB1 + bb);
            mma16816(acc[nt], ah, bh2);
            mma16816(acc[nt], ah, bl2);
            mma16816(acc[nt], al, bh2);
        }
    }

    const float S = 1.f / 3.f;
    int o0 = strip * 64 + wm * 16;
#pragma unroll
    for (int nt = 0; nt < 13; nt++) {
        int t = wn * 104 + nt * 8 + tg * 2;
#pragma unroll
        for (int rr = 0; rr < 2; rr++) {
            int o = o0 + gq + rr * 8;
            int ml = o & 15;
            int pm = ((ml & 2) << 2) | ((ml & 12) >> 1) | (ml & 1);
            int operm = (o & ~15) | pm;
            float v0 = acc[nt][rr * 2 + 0] * S, v1 = acc[nt][rr * 2 + 1] * S;
            uint32_t hp = (uint32_t)bf16h(v0) | ((uint32_t)bf16h(v1) << 16);
            uint32_t lp = (uint32_t)bf16l(v0) | ((uint32_t)bf16l(v1) << 16);
            size_t off = ((size_t)m * EN + operm) * EK + t;
            *(uint32_t*)&g_Mbh[off] = hp;
            *(uint32_t*)&g_Mbl[off] = lp;
        }
    }
}

// ---------------- edge messages: resident-B quarters ----------------
#define EQ 112                          // cols per quarter
#define ET2 128                         // edge rows per tile
#define XSTR 432                        // row stride (416 data + 16 pad)
#define EA_BYTES (ET2 * XSTR)           // 110592
#define EB_BYTES (EQ * XSTR)            // 48384
#define EDGE_SMEM2 (2 * EA_BYTES + 2 * EB_BYTES)  // 207360

__global__ void __launch_bounds__(256) k_edge_mma(
    const float* __restrict__ ent_emb, const int* __restrict__ src,
    const int* __restrict__ dst, const float* __restrict__ nrm) {
    extern __shared__ char sm[];
    uint32_t sbase = smem_u32(sm);
    const uint32_t A_HI = 0, A_LO = EA_BYTES, B_HI = 2 * EA_BYTES,
                   B_LO = 2 * EA_BYTES + EB_BYTES;
    __shared__ int s_src[ET2];
    __shared__ int s_dst[ET2];
    __shared__ float s_nrm[ET2];

    int gq4 = blockIdx.y;
    int g = gq4 >> 2, q = gq4 & 3;
    int base = g_off[g];
    int ng = g_off[g + 1] - base;
    if (ng == 0) return;
    int tid = threadIdx.x, wid = tid >> 5, lane = tid & 31;
    int gq = lane >> 2, tg = lane & 3;
    int mat = lane >> 3, r = lane & 7;
    uint32_t aoff = (uint32_t)(((mat & 1) * 8 + r) * XSTR + (mat >> 1) * 16);
    uint32_t boff = (uint32_t)(r * XSTR + ((lane >> 3) & 1) * 16);
    const __nv_bfloat16* Bh = g_Mbh + ((size_t)g * EN + q * EQ) * EK;
    const __nv_bfloat16* Bl = g_Mbl + ((size_t)g * EN + q * EQ) * EK;

    // stage resident B quarter once (EQ rows x 416B x 2 planes)
    for (int idx = tid; idx < EQ * 26 * 2; idx += 256) {
        int p = (idx >= EQ * 26) ? 1 : 0;
        int rem = idx - p * EQ * 26;
        int row = rem / 26, seg = rem - row * 26;
        const __nv_bfloat16* gB = p ? Bl : Bh;
        uint32_t d = (p ? B_LO : B_HI) + row * XSTR + seg * 16;
        *(uint4*)(sm + d) = *(const uint4*)&gB[(size_t)row * EK + seg * 8];
    }

    for (int t0 = 0; t0 < ng; t0 += ET2) {
        int cnt = min(ET2, ng - t0);
        __syncthreads();  // covers B visibility (first iter) + s_dst/A reuse
        if (tid < ET2) {
            if (tid < cnt) {
                int e = g_eidx[base + t0 + tid];
                s_src[tid] = src[e];
                s_dst[tid] = dst[e];
                s_nrm[tid] = nrm[e];
            } else {
                s_src[tid] = 0;
                s_dst[tid] = 0;
                s_nrm[tid] = 0.f;
            }
        }
        __syncthreads();
        for (int idx = tid; idx < ET2 * 26; idx += 256) {
            int row = idx / 26, seg = idx - row * 26;
            uint32_t hi4[4] = {0, 0, 0, 0}, lo4[4] = {0, 0, 0, 0};
            if (seg < 25) {
                const float* p = &ent_emb[(size_t)s_src[row] * DI + seg * 8];
                float nv = s_nrm[row];
#pragma unroll
                for (int qd = 0; qd < 4; qd++) {
                    float v0 = p[qd * 2] * nv, v1 = p[qd * 2 + 1] * nv;
                    hi4[qd] = (uint32_t)bf16h(v0) | ((uint32_t)bf16h(v1) << 16);
                    lo4[qd] = (uint32_t)bf16l(v0) | ((uint32_t)bf16l(v1) << 16);
                }
            }
            uint32_t so = (uint32_t)(row * XSTR + seg * 16);
            *(uint4*)(sm + A_HI + so) = make_uint4(hi4[0], hi4[1], hi4[2], hi4[3]);
            *(uint4*)(sm + A_LO + so) = make_uint4(lo4[0], lo4[1], lo4[2], lo4[3]);
        }
        __syncthreads();

        float acc[14][4];
#pragma unroll
        for (int nt = 0; nt < 14; nt++)
#pragma unroll
            for (int qd = 0; qd < 4; qd++) acc[nt][qd] = 0.f;

        for (int kc = 0; kc < 13; kc++) {
            uint32_t ah[4], al[4];
            uint32_t ab = (uint32_t)((wid * 16) * XSTR + kc * 32) + aoff;
            ldsm_x4(ah, sbase + A_HI + ab);
            ldsm_x4(al, sbase + A_LO + ab);
#pragma unroll
            for (int nt = 0; nt < 14; nt++) {
                uint32_t bh2[2], bl2[2];
                uint32_t bb = (uint32_t)((nt * 8) * XSTR + kc * 32) + boff;
                ldsm_x2(bh2, sbase + B_HI + bb);
                ldsm_x2(bl2, sbase + B_LO + bb);
                mma16816(acc[nt], ah, bh2);
                mma16816(acc[nt], ah, bl2);
                mma16816(acc[nt], al, bh2);
            }
        }

        int er0 = wid * 16 + gq;
        int er1 = er0 + 8;
#pragma unroll
        for (int qt = 0; qt < 7; qt++) {
            int c = q * EQ + qt * 16 + tg * 4;
            if (c < DO) {
                float* a0 = acc[2 * qt];
                float* a1 = acc[2 * qt + 1];
                if (er0 < cnt)
                    red4(&g_x[(size_t)s_dst[er0] * DO + c], a0[0], a0[1], a1[0], a1[1]);
                if (er1 < cnt)
                    red4(&g_x[(size_t)s_dst[er1] * DO + c], a0[2], a0[3], a1[2], a1[3]);
            }
        }
    }
}

// ---------------- self-loop via mma.sync: x = agg + loop + bias ----------------
#define ASTR 432
#define BSTR 48
#define LA_BYTES (64 * ASTR)
#define LB_BYTES (EN * BSTR)
#define LOOP_SMEM (2 * LA_BYTES + 2 * LB_BYTES)

__global__ void __launch_bounds__(256) k_loopx_mma(
    const float* __restrict__ ent_emb, const float* __restrict__ bias_w) {
    extern __shared__ char sm[];
    uint32_t sbase = smem_u32(sm);
    const uint32_t A_HI = 0, A_LO = LA_BYTES, B_HI = 2 * LA_BYTES, B_LO = 2 * LA_BYTES + LB_BYTES;

    int tid = threadIdx.x, wid = tid >> 5, lane = tid & 31;
    int wm = wid >> 2, wn = wid & 3;
    int gq = lane >> 2, tg = lane & 3;
    int mat = lane >> 3, r = lane & 7;
    uint32_t aoff = (uint32_t)(((mat & 1) * 8 + r) * ASTR + (mat >> 1) * 16);
    uint32_t boff = (uint32_t)(r * BSTR + ((lane >> 3) & 1) * 16);
    const __nv_bfloat16* Bh = g_Mbh + (size_t)NGROUP * EN * EK;
    const __nv_bfloat16* Bl = g_Mbl + (size_t)NGROUP * EN * EK;

    int row0 = blockIdx.x * 64;
    int cnt = min(64, NE - row0);

    for (int idx = tid; idx < 64 * 26; idx += 256) {
        int row = idx / 26, seg = idx - row * 26;
        uint32_t hi4[4] = {0, 0, 0, 0}, lo4[4] = {0, 0, 0, 0};
        if (seg < 25 && row < cnt) {
            const float* p = &ent_emb[(size_t)(row0 + row) * DI + seg * 8];
#pragma unroll
            for (int qd = 0; qd < 4; qd++) {
                float v0 = p[qd * 2], v1 = p[qd * 2 + 1];
                hi4[qd] = (uint32_t)bf16h(v0) | ((uint32_t)bf16h(v1) << 16);
                lo4[qd] = (uint32_t)bf16l(v0) | ((uint32_t)bf16l(v1) << 16);
            }
        }
        uint32_t so = (uint32_t)(row * ASTR + seg * 16);
        *(uint4*)(sm + A_HI + so) = make_uint4(hi4[0], hi4[1], hi4[2], hi4[3]);
        *(uint4*)(sm + A_LO + so) = make_uint4(lo4[0], lo4[1], lo4[2], lo4[3]);
    }

    float acc[2][14][4];
#pragma unroll
    for (int mt = 0; mt < 2; mt++)
#pragma unroll
        for (int nt = 0; nt < 14; nt++)
#pragma unroll
            for (int qd = 0; qd < 4; qd++) acc[mt][nt][qd] = 0.f;

    for (int kc = 0; kc < 13; kc++) {
        __syncthreads();
        for (int idx = tid; idx < EN * 2; idx += 256) {
            int o = idx >> 1, half = idx & 1;
            size_t goff = (size_t)o * EK + kc * 16 + half * 8;
            *(uint4*)(sm + B_HI + o * BSTR + half * 16) = *(const uint4*)&Bh[goff];
            *(uint4*)(sm + B_LO + o * BSTR + half * 16) = *(const uint4*)&Bl[goff];
        }
        __syncthreads();
        uint32_t ah[2][4], al[2][4];
#pragma unroll
        for (int mt = 0; mt < 2; mt++) {
            uint32_t ab = (uint32_t)((wm * 32 + mt * 16) * ASTR + kc * 32) + aoff;
            ldsm_x4(ah[mt], sbase + A_HI + ab);
            ldsm_x4(al[mt], sbase + A_LO + ab);
        }
#pragma unroll
        for (int nt = 0; nt < 14; nt++) {
            uint32_t bh2[2], bl2[2];
            uint32_t bb = (uint32_t)((wn * 112 + nt * 8) * BSTR) + boff;
            ldsm_x2(bh2, sbase + B_HI + bb);
            ldsm_x2(bl2, sbase + B_LO + bb);
#pragma unroll
            for (int mt = 0; mt < 2; mt++) {
                mma16816(acc[mt][nt], ah[mt], bh2);
                mma16816(acc[mt][nt], ah[mt], bl2);
                mma16816(acc[mt][nt], al[mt], bh2);
            }
        }
    }

#pragma unroll
    for (int mt = 0; mt < 2; mt++) {
        int er0 = wm * 32 + mt * 16 + gq;
        int er1 = er0 + 8;
#pragma unroll
        for (int qt = 0; qt < 7; qt++) {
            int c = wn * 112 + qt * 16 + tg * 4;
            if (c < DO) {
                float4 b4 = *(const float4*)&bias_w[c];
                float* a0 = acc[mt][2 * qt];
                float* a1 = acc[mt][2 * qt + 1];
                if (er0 < cnt) {
                    float* xr = &g_x[(size_t)(row0 + er0) * DO + c];
                    float4 cur = *(float4*)xr;
                    *(float4*)xr = make_float4(cur.x + a0[0] + b4.x, cur.y + a0[1] + b4.y,
                                               cur.z + a1[0] + b4.z, cur.w + a1[1] + b4.w);
                }
                if (er1 < cnt) {
                    float* xr = &g_x[(size_t)(row0 + er1) * DO + c];
                    float4 cur = *(float4*)xr;
                    *(float4*)xr = make_float4(cur.x + a0[2] + b4.x, cur.y + a0[3] + b4.y,
                                               cur.z + a1[2] + b4.z, cur.w + a1[3] + b4.w);
                }
            }
        }
    }
}

// ---------------- BN column stats ----------------
__global__ void k_stats() {
    int c = threadIdx.x;
    float s = 0.f, q = 0.f;
    for (int r = blockIdx.x; r < NE; r += gridDim.x) {
        float v = g_x[(size_t)r * DO + c];
        s += v;
        q += v * v;
    }
    atomicAdd(&g_stats[c], s);
    atomicAdd(&g_stats[DO + c], q);
}

__global__ void k_bn(const float* __restrict__ gamma, const float* __restrict__ beta) {
    int c = threadIdx.x;
    if (c < DO) {
        float mean = g_stats[c] / (float)NE;
        float var = g_stats[DO + c] / (float)NE - mean * mean;
        float sc = gamma[c] * rsqrtf(var + BN_EPS);
        g_scale[c] = sc;
        g_shift[c] = beta[c] - mean * sc;
    }
}

// ---------------- r = rel_emb @ w_rel ----------------
__global__ void k_rel(const float* __restrict__ rel_emb, const float* __restrict__ w_rel) {
    int idx = blockIdx.x * blockDim.x + threadIdx.x;
    if (idx < NR * DO) {
        int row = idx / DO, col = idx - row * DO;
        float acc = 0.f;
        for (int k = 0; k < DI; k++)
            acc = fmaf(rel_emb[row * DI + k], w_rel[k * DO + col], acc);
        g_r[idx] = acc;
    }
}

// ---------------- obj = tanh(bn(x[head])) * r[rel] -> bf16 hi/lo ----------------
__global__ void k_obj(const int* __restrict__ triples) {
    int i = blockIdx.x;
    int c = threadIdx.x;
    float v = 0.f;
    if (c < DO) {
        int h = triples[3 * i], rl = triples[3 * i + 1];
        float t = tanhf(g_x[(size_t)h * DO + c] * g_scale[c] + g_shift[c]);
        v = t * g_r[rl * DO + c];
    }
    __nv_bfloat16 hi = __float2bfloat16(v);
    g_obj_hi[i * KP + c] = hi;
    g_obj_lo[i * KP + c] = __float2bfloat16(v - __bfloat162float(hi));
}

// ---------------- emb -> bf16 hi/lo, padded to KP ----------------
__global__ void k_split_emb(const float* __restrict__ emb) {
    int row = blockIdx.x;
    int c = threadIdx.x;
    float v = (c < DO) ? emb[(size_t)row * DO + c] : 0.f;
    __nv_bfloat16 hi = __float2bfloat16(v);
    size_t idx = (size_t)row * KP + c;
    g_emb_hi[idx] = hi;
    g_emb_lo[idx] = __float2bfloat16(v - __bfloat162float(hi));
}

// ---------------- score via mma.sync ----------------
#define SSTR 144
#define PLANE (128 * SSTR)
__global__ void __launch_bounds__(256) k_score_mma(
    const float* __restrict__ ebias, float* __restrict__ out) {
    extern __shared__ char sm[];
    uint32_t sbase = smem_u32(sm);
    const uint32_t A_HI = 0, A_LO = PLANE, B_HI = 2 * PLANE, B_LO = 3 * PLANE;

    int tid = threadIdx.x, wid = tid >> 5, lane = tid & 31;
    int wm = wid >> 2, wn = wid & 3;
    int i0 = blockIdx.x * 128;
    int e0 = blockIdx.y * 128;
    int g = lane >> 2, tg = lane & 3;

    int mat = lane >> 3, r = lane & 7;
    uint32_t aoff = (uint32_t)(((mat & 1) * 8 + r) * SSTR + (mat >> 1) * 16);
    uint32_t boff = (uint32_t)(r * SSTR + ((lane >> 3) & 1) * 16);

    float acc[4][4][4] = {};

    for (int ch = 0; ch < 7; ch++) {
        int k0 = ch * 64;
        __syncthreads();
        const uint4 z4 = make_uint4(0, 0, 0, 0);
        for (int idx = tid; idx < 128 * 8; idx += 256) {
            int row = idx >> 3, seg = idx & 7;
            uint32_t so = (uint32_t)(row * SSTR + seg * 16);
            *(uint4*)(sm + A_HI + so) =
                *(const uint4*)&g_obj_hi[(size_t)(i0 + row) * KP + k0 + seg * 8];
            *(uint4*)(sm + A_LO + so) =
                *(const uint4*)&g_obj_lo[(size_t)(i0 + row) * KP + k0 + seg * 8];
            int e = e0 + row;
            uint4 vh = z4, vl = z4;
            if (e < NE) {
                vh = *(const uint4*)&g_emb_hi[(size_t)e * KP + k0 + seg * 8];
                vl = *(const uint4*)&g_emb_lo[(size_t)e * KP + k0 + seg * 8];
            }
            *(uint4*)(sm + B_HI + so) = vh;
            *(uint4*)(sm + B_LO + so) = vl;
        }
        __syncthreads();

#pragma unroll
        for (int ks = 0; ks < 4; ks++) {
            uint32_t ah[4][4], al[4][4], bh[4][2], bl[4][2];
#pragma unroll
            for (int mt = 0; mt < 4; mt++) {
                uint32_t ab = (uint32_t)((wm * 64 + mt * 16) * SSTR + ks * 32) + aoff;
                ldsm_x4(ah[mt], sbase + A_HI + ab);
                ldsm_x4(al[mt], sbase + A_LO + ab);
            }
#pragma unroll
            for (int nt = 0; nt < 4; nt++) {
                uint32_t bb = (uint32_t)((wn * 32 + nt * 8) * SSTR + ks * 32) + boff;
                ldsm_x2(bh[nt], sbase + B_HI + bb);
                ldsm_x2(bl[nt], sbase + B_LO + bb);
            }
#pragma unroll
            for (int mt = 0; mt < 4; mt++)
#pragma unroll
                for (int nt = 0; nt < 4; nt++) {
                    mma16816(acc[mt][nt], ah[mt], bh[nt]);
                    mma16816(acc[mt][nt], ah[mt], bl[nt]);
                    mma16816(acc[mt][nt], al[mt], bh[nt]);
                }
        }
    }

#pragma unroll
    for (int mt = 0; mt < 4; mt++) {
        int row = i0 + wm * 64 + mt * 16 + g;
#pragma unroll
        for (int nt = 0; nt < 4; nt++) {
            int col = e0 + wn * 32 + nt * 8 + tg * 2;
            if (col < NE) {
                float b0 = ebias[col], b1 = ebias[col + 1];
                float2 v0;
                v0.x = 1.f / (1.f + __expf(-(acc[mt][nt][0] + b0)));
                v0.y = 1.f / (1.f + __expf(-(acc[mt][nt][1] + b1)));
                *(float2*)&out[(size_t)row * NE + col] = v0;
                float2 v1;
                v1.x = 1.f / (1.f + __expf(-(acc[mt][nt][2] + b0)));
                v1.y = 1.f / (1.f + __expf(-(acc[mt][nt][3] + b1)));
                *(float2*)&out[(size_t)(row + 8) * NE + col] = v1;
            }
        }
    }
}

// ---------------- launch ----------------
extern "C" void kernel_launch(void* const* d_in, const int* in_sizes, int n_in,
                              void* d_out, int out_size) {
    const float* ent_emb  = (const float*)d_in[0];
    const float* rel_emb  = (const float*)d_in[1];
    const float* in_w     = (const float*)d_in[2];
    const float* out_w    = (const float*)d_in[3];
    const float* loop_w   = (const float*)d_in[4];
    const float* w_rel    = (const float*)d_in[5];
    const float* loop_rel = (const float*)d_in[6];
    const float* bias_w   = (const float*)d_in[7];
    const float* bn_gamma = (const float*)d_in[8];
    const float* bn_beta  = (const float*)d_in[9];
    const float* emb_ent  = (const float*)d_in[10];
    const float* ent_bias = (const float*)d_in[11];
    const int*   src      = (const int*)d_in[12];
    const int*   dst      = (const int*)d_in[13];
    const int*   et       = (const int*)d_in[14];
    const float* enorm    = (const float*)d_in[15];
    const int*   triples  = (const int*)d_in[16];
    float* out = (float*)d_out;

    cudaFuncSetAttribute(k_edge_mma, cudaFuncAttributeMaxDynamicSharedMemorySize, EDGE_SMEM2);
    cudaFuncSetAttribute(k_loopx_mma, cudaFuncAttributeMaxDynamicSharedMemorySize, LOOP_SMEM);
    const int SM_SCORE = 4 * PLANE;
    cudaFuncSetAttribute(k_score_mma, cudaFuncAttributeMaxDynamicSharedMemorySize, SM_SCORE);

    k_zero<<<4096, 256>>>();
    k_hist<<<(NEDGE + 255) / 256, 256>>>(et);
    k_scan<<<1, 1024>>>();
    k_scatter<<<(NEDGE + 255) / 256, 256>>>(et);
    k_splitW<<<dim3(448, 3), 256>>>(in_w, out_w, loop_w);
    k_M_mma<<<dim3(7, 801), 256>>>(rel_emb, loop_rel);
    k_split_emb<<<NE, KP>>>(emb_ent);
    k_edge_mma<<<dim3(1, 4 * NGROUP), 256, EDGE_SMEM2>>>(ent_emb, src, dst, enorm);
    k_loopx_mma<<<(NE + 63) / 64, 256, LOOP_SMEM>>>(ent_emb, bias_w);
    k_stats<<<256, 400>>>();
    k_bn<<<1, 512>>>(bn_gamma, bn_beta);
    k_rel<<<(NR * DO + 255) / 256, 256>>>(rel_emb, w_rel);
    k_obj<<<NB, KP>>>(triples);
    k_score_mma<<<dim3(NB / 128, (NE + 127) / 128), 256, SM_SCORE>>>(ent_bias, out);
}